// round 11
// baseline (speedup 1.0000x reference)
#include <cuda_runtime.h>
#include <math.h>

#define NLEADS 61
#define NB 128
typedef unsigned long long ull;

__device__ float g_preds[NB * NLEADS * 3];

// ---------------- packed fp32x2 ops (Blackwell) ----------------
__device__ __forceinline__ ull ffma2(ull a, ull b, ull c) {
    ull d;
    asm("fma.rn.f32x2 %0, %1, %2, %3;" : "=l"(d) : "l"(a), "l"(b), "l"(c));
    return d;
}
__device__ __forceinline__ ull pk(float lo, float hi) {
    ull r;
    asm("mov.b64 %0, {%1, %2};" : "=l"(r) : "f"(lo), "f"(hi));
    return r;
}
__device__ __forceinline__ float2 upk(ull v) {
    float2 f;
    asm("mov.b64 {%0, %1}, %2;" : "=f"(f.x), "=f"(f.y) : "l"(v));
    return f;
}
__device__ __forceinline__ float hsum(ull v) {
    const float2 f = upk(v);
    return f.x + f.y;
}

// ---- shared memory layout (floats), total 13112 fl = 52.4 KB -> 4 CTAs/SM ----
#define OFF_A1P 0        // [8][18][68] = 9792 fl
#define OFF_W1D 9792     // 192 fl (dup pairs)
#define OFF_W2D 9984     // 3072 fl (dup pairs)
#define OFF_B1  13056    // 8
#define OFF_B2  13064    // 16
#define OFF_B3  13080    // 32
#define SMEM_FLOATS 13112
#define SMEM_BYTES (SMEM_FLOATS*4)   // 52448

// aliases inside the A1P region (valid after L2's read-complete sync)
#define OFF_W3  0        // 6144 fl (RAW w3; natural tap pairs)
#define OFF_A2P 6144     // [16][6][20] = 1920 fl (16B aligned)
#define OFF_A3  8064     // 256 fl (16B aligned)
#define OFF_A4  8320     // 64
#define OFF_LG  8384     // 4

__global__ void __launch_bounds__(256, 4)
lead_forward_kernel(const float* __restrict__ x,
                    const float* __restrict__ w1g, const float* __restrict__ b1g,
                    const float* __restrict__ w2g, const float* __restrict__ b2g,
                    const float* __restrict__ w3g, const float* __restrict__ b3g,
                    const float* __restrict__ w4g, const float* __restrict__ b4g,
                    const float* __restrict__ fcw, const float* __restrict__ fcb)
{
    extern __shared__ float sm[];
    float*  sA1p = sm + OFF_A1P;
    float4* A1p4 = (float4*)sA1p;
    float*  sA2p = sm + OFF_A2P;
    float*  sA3  = sm + OFF_A3;
    float*  sA4  = sm + OFF_A4;
    float*  sLg  = sm + OFF_LG;
    float*  sw1d = sm + OFF_W1D;
    float*  sw2d = sm + OFF_W2D;
    float*  sw3  = sm + OFF_W3;
    float*  sb1  = sm + OFF_B1;
    float*  sb2  = sm + OFF_B2;
    float*  sb3  = sm + OFF_B3;

    const int tid = threadIdx.x;
    const int b = blockIdx.x;
    const int l = blockIdx.y;
    const float4 z4 = make_float4(0.f,0.f,0.f,0.f);
    const float2 z2 = make_float2(0.f, 0.f);
    const float2* x2 = (const float2*)(x + ((size_t)(b*NLEADS + l))*8000);

    // ---- init: zero ONLY the A1p halo ----
    for (int i = tid; i < 8*2*17; i += 256) {
        const int pl = i / 34, sub = i % 34;
        const int row = (sub / 17) * 17;          // 0 or 17
        A1p4[pl*306 + row*17 + (sub % 17)] = z4;
    }
    if (tid < 128) {
        const int pl = tid >> 4, r = (tid & 15) + 1;
        sA1p[pl*1224 + r*68] = 0.0f;
        A1p4[pl*306 + r*17 + 16] = z4;
    }
    // ---- stage dup weight pairs + biases ----
    if (tid < 96) {
        const float v = w1g[l*96 + tid];
        ((float2*)sw1d)[tid] = make_float2(v, v);
    }
    #pragma unroll
    for (int k = 0; k < 6; k++) {
        const int i = tid + k*256;
        if (i < 1536) {
            const float v = w2g[l*1536 + i];
            ((float2*)sw2d)[i] = make_float2(v, v);
        }
    }
    if (tid < 8)  sb1[tid] = b1g[l*8 + tid];
    if (tid < 16) sb2[tid] = b2g[l*16 + tid];
    if (tid < 32) sb3[tid] = b3g[l*32 + tid];
    __syncthreads();

    // =====================================================================
    // Layer 1 (pooled-row PAIRS): conv (1->8, 3x4, s(1,2), pad (1,1)(2,2))
    // + pool + relu -> pooled (8,16,63) into A1p. Direct global-x patches.
    // Interior fast path: pp in 1..6 and pw in 1..61 -> no predicates.
    // =====================================================================
    for (int pair = tid; pair < 8*63; pair += 256) {
        const int pp = pair / 63, pw = pair - pp*63;
        ull P[6][4];
        const float2* rp0 = x2 + (4*pp - 1)*125 + (2*pw - 1);
        if (pp > 0 && pp < 7 && pw > 0 && pw < 62) {
            #pragma unroll
            for (int r = 0; r < 6; r++) {
                const float2* rp = rp0 + r*125;
                const float2 pA = rp[0], pB = rp[1], pC = rp[2];
                P[r][0] = pk(pA.x, pB.x);
                P[r][1] = pk(pA.y, pB.y);
                P[r][2] = pk(pB.x, pC.x);
                P[r][3] = pk(pB.y, pC.y);
            }
        } else {
            #pragma unroll
            for (int r = 0; r < 6; r++) {
                const int sr = 4*pp - 1 + r;
                const bool rv = (sr >= 0) & (sr < 32);
                const float2* rp = rp0 + r*125;
                const float2 pA = (rv && pw > 0)  ? rp[0] : z2;
                const float2 pB =  rv             ? rp[1] : z2;
                const float2 pC = (rv && pw < 62) ? rp[2] : z2;
                P[r][0] = pk(pA.x, pB.x);
                P[r][1] = pk(pA.y, pB.y);
                P[r][2] = pk(pB.x, pC.x);
                P[r][3] = pk(pB.y, pC.y);
            }
        }
        #pragma unroll
        for (int co = 0; co < 8; co++) {
            const ulonglong2* wq = (const ulonglong2*)(sw1d + co*24);
            ull a0=0ull, a1=0ull, a2=0ull, a3=0ull;
            #pragma unroll
            for (int j = 0; j < 6; j++) {
                const ulonglong2 q = wq[j];
                {   const int t = 2*j, kh = t>>2, kw = t&3;
                    a0 = ffma2(P[kh+0][kw], q.x, a0);
                    a1 = ffma2(P[kh+1][kw], q.x, a1);
                    a2 = ffma2(P[kh+2][kw], q.x, a2);
                    a3 = ffma2(P[kh+3][kw], q.x, a3); }
                {   const int t = 2*j+1, kh = t>>2, kw = t&3;
                    a0 = ffma2(P[kh+0][kw], q.y, a0);
                    a1 = ffma2(P[kh+1][kw], q.y, a1);
                    a2 = ffma2(P[kh+2][kw], q.y, a2);
                    a3 = ffma2(P[kh+3][kw], q.y, a3); }
            }
            const float bias = sb1[co];
            const float2 f0 = upk(a0), f1 = upk(a1), f2 = upk(a2), f3 = upk(a3);
            const float m0 = fmaxf(fmaxf(f0.x, f0.y), fmaxf(f1.x, f1.y)) + bias;
            const float m1 = fmaxf(fmaxf(f2.x, f2.y), fmaxf(f3.x, f3.y)) + bias;
            sA1p[co*(18*68) + (2*pp+1)*68 + (pw+1)] = fmaxf(m0, 0.0f);
            sA1p[co*(18*68) + (2*pp+2)*68 + (pw+1)] = fmaxf(m1, 0.0f);
        }
    }
    __syncthreads();

    // =====================================================================
    // Layer 2 (R8 mapping): conv (8->16, 4x3, s(2,2), pad 1) + pool + relu
    // (8,16,63) -> pooled (16,4,16). thread = (cg of 4 co) x (64 pos).
    // =====================================================================
    {
        const int pos = tid & 63;
        const int cg  = tid >> 6;
        const int ph = pos >> 4, pw = pos & 15;
        ull a0[4], a1[4];
        #pragma unroll
        for (int i = 0; i < 4; i++) { a0[i] = 0ull; a1[i] = 0ull; }

        #pragma unroll 1
        for (int ci = 0; ci < 8; ci++) {
            ull P[6][3];
            #pragma unroll
            for (int r = 0; r < 6; r++) {
                const int sr = 4*ph + r;
                const float4 v = A1p4[ci*(18*17) + sr*17 + pw];
                const float  e = sA1p[ci*(18*68) + sr*68 + 4*pw + 4];
                P[r][0] = pk(v.x, v.z);
                P[r][1] = pk(v.y, v.w);
                P[r][2] = pk(v.z, e);
            }
            #pragma unroll
            for (int i = 0; i < 4; i++) {
                const int co = cg*4 + i;
                const ulonglong2* wq = (const ulonglong2*)(sw2d + (co*8 + ci)*24);
                #pragma unroll
                for (int j = 0; j < 6; j++) {
                    const ulonglong2 q = wq[j];
                    const int t0 = 2*j, t1 = 2*j + 1;
                    a0[i] = ffma2(P[t0/3][t0%3],     q.x, a0[i]);
                    a1[i] = ffma2(P[t0/3 + 2][t0%3], q.x, a1[i]);
                    a0[i] = ffma2(P[t1/3][t1%3],     q.y, a0[i]);
                    a1[i] = ffma2(P[t1/3 + 2][t1%3], q.y, a1[i]);
                }
            }
        }
        __syncthreads();   // ALL A1p reads done -> safe to overwrite region
        #pragma unroll
        for (int i = 0; i < 4; i++) {
            const int co = cg*4 + i;
            const float2 f0 = upk(a0[i]), f1 = upk(a1[i]);
            const float m = fmaxf(fmaxf(f0.x, f0.y), fmaxf(f1.x, f1.y)) + sb2[co];
            sA2p[co*(6*20) + (ph+1)*20 + (pw+1)] = fmaxf(m, 0.0f);
        }
        // zero A2p halo (rows 0,5 and cols 0,17..19 of each [6][20] plane)
        for (int i = tid; i < 16*20; i += 256) {
            const int ci2 = i / 20, c = i % 20;
            sA2p[ci2*120 + 0*20 + c]  = 0.0f;
            sA2p[ci2*120 + 5*20 + c]  = 0.0f;
        }
        for (int i = tid; i < 16*4; i += 256) {
            const int ci2 = i / 4, r = (i & 3) + 1;
            float* row = sA2p + ci2*120 + r*20;
            row[0] = 0.0f; row[17] = 0.0f; row[18] = 0.0f; row[19] = 0.0f;
        }
    }
    // stage RAW w3 into freed A1p head (coalesced float4)
    {
        const float4* w34 = (const float4*)(w3g + (size_t)l*6144);
        #pragma unroll
        for (int k = 0; k < 6; k++) ((float4*)sw3)[tid + k*256] = w34[tid + k*256];
    }
    __syncthreads();

    // =====================================================================
    // Layer 3 (TAP-PAIRED): conv (16->32, 3x4, s(1,2), pad 1) + pool + relu
    // (16,4,16) -> pooled (32,2,4). thread = (co-pair of 16) x (8 pos).
    // =====================================================================
    if (tid < 128) {
        const int cp  = tid >> 3;
        const int pos = tid & 7;
        const int ph = pos >> 2, pw = pos & 3;
        ull vA0[2], vA1[2], vB0[2], vB1[2];
        #pragma unroll
        for (int c = 0; c < 2; c++) { vA0[c]=vA1[c]=vB0[c]=vB1[c]=0ull; }

        #pragma unroll 1
        for (int ci = 0; ci < 16; ci++) {
            ull p0[4], p1[4], p2[4];
            #pragma unroll
            for (int r = 0; r < 4; r++) {
                const int base = ci*120 + (2*ph + r)*20 + 4*pw;
                const ulonglong2 q = *(const ulonglong2*)(sA2p + base);
                p0[r] = q.x; p1[r] = q.y;
                p2[r] = *(const ull*)(sA2p + base + 4);
            }
            #pragma unroll
            for (int c = 0; c < 2; c++) {
                const int co = cp*2 + c;
                const ulonglong2* wq = (const ulonglong2*)(sw3 + (co*16 + ci)*12);
                const ulonglong2 q0 = wq[0];
                const ulonglong2 q1 = wq[1];
                const ulonglong2 q2 = wq[2];
                vA0[c] = ffma2(p0[0], q0.x, vA0[c]); vA0[c] = ffma2(p1[0], q0.y, vA0[c]);
                vA0[c] = ffma2(p0[1], q1.x, vA0[c]); vA0[c] = ffma2(p1[1], q1.y, vA0[c]);
                vA0[c] = ffma2(p0[2], q2.x, vA0[c]); vA0[c] = ffma2(p1[2], q2.y, vA0[c]);

                vA1[c] = ffma2(p0[1], q0.x, vA1[c]); vA1[c] = ffma2(p1[1], q0.y, vA1[c]);
                vA1[c] = ffma2(p0[2], q1.x, vA1[c]); vA1[c] = ffma2(p1[2], q1.y, vA1[c]);
                vA1[c] = ffma2(p0[3], q2.x, vA1[c]); vA1[c] = ffma2(p1[3], q2.y, vA1[c]);

                vB0[c] = ffma2(p1[0], q0.x, vB0[c]); vB0[c] = ffma2(p2[0], q0.y, vB0[c]);
                vB0[c] = ffma2(p1[1], q1.x, vB0[c]); vB0[c] = ffma2(p2[1], q1.y, vB0[c]);
                vB0[c] = ffma2(p1[2], q2.x, vB0[c]); vB0[c] = ffma2(p2[2], q2.y, vB0[c]);

                vB1[c] = ffma2(p1[1], q0.x, vB1[c]); vB1[c] = ffma2(p2[1], q0.y, vB1[c]);
                vB1[c] = ffma2(p1[2], q1.x, vB1[c]); vB1[c] = ffma2(p2[2], q1.y, vB1[c]);
                vB1[c] = ffma2(p1[3], q2.x, vB1[c]); vB1[c] = ffma2(p2[3], q2.y, vB1[c]);
            }
        }
        #pragma unroll
        for (int c = 0; c < 2; c++) {
            const int co = cp*2 + c;
            const float a0 = hsum(vA0[c]), a1 = hsum(vA1[c]);
            const float b0 = hsum(vB0[c]), b1 = hsum(vB1[c]);
            const float m = fmaxf(fmaxf(a0, b0), fmaxf(a1, b1)) + sb3[co];
            sA3[co*8 + pos] = fmaxf(m, 0.0f);
        }
    }
    __syncthreads();

    // =====================================================================
    // Layer 4: dot(256) per co. QUARTER-WARP mapping: 4 lanes per co, each
    // lane dots a contiguous 64-fl slice loaded directly as ulonglong2
    // (zero pk MOVs), then a 2-level shuffle reduce.
    // =====================================================================
    {
        const int warp = tid >> 5, lane = tid & 31;
        const int j = lane >> 2, q = lane & 3;
        const int co = warp*8 + j;
        const ulonglong2* wr = (const ulonglong2*)(w4g + ((size_t)(l*64 + co))*256) + q*16;
        const ulonglong2* ar = (const ulonglong2*)sA3 + q*16;
        ull acc = 0ull;
        #pragma unroll
        for (int k = 0; k < 16; k++) {
            const ulonglong2 wv = wr[k];
            const ulonglong2 av = ar[k];
            acc = ffma2(wv.x, av.x, acc);
            acc = ffma2(wv.y, av.y, acc);
        }
        float s = hsum(acc);
        s += __shfl_xor_sync(0xffffffffu, s, 1);
        s += __shfl_xor_sync(0xffffffffu, s, 2);
        if (q == 0) sA4[co] = s + b4g[l*64 + co];
    }
    __syncthreads();

    // ---- FC (64->3): one warp per class ----
    if (tid < 96) {
        const int c = tid >> 5, lane = tid & 31;
        const float* w = fcw + ((size_t)(l*3 + c))*64;
        float a = w[lane]*sA4[lane] + w[lane+32]*sA4[lane+32];
        #pragma unroll
        for (int o = 16; o; o >>= 1) a += __shfl_xor_sync(0xffffffffu, a, o);
        if (lane == 0) sLg[c] = a + fcb[l*3 + c];
    }
    __syncthreads();

    // ---- softmax, one thread ----
    if (tid == 0) {
        const float m = fmaxf(sLg[0], fmaxf(sLg[1], sLg[2]));
        const float e0 = expf(sLg[0]-m), e1 = expf(sLg[1]-m), e2 = expf(sLg[2]-m);
        const float inv = 1.0f / (e0 + e1 + e2);
        float* outp = g_preds + ((size_t)(b*NLEADS + l))*3;
        outp[0] = e0*inv; outp[1] = e1*inv; outp[2] = e2*inv;
    }
}

// =====================================================================
// Fusion loss in log2 space. One block per batch, one warp per class.
// =====================================================================
__global__ void loss_kernel(float* __restrict__ out)
{
    const int b = blockIdx.x;
    const int c = threadIdx.x >> 5;
    const int lane = threadIdx.x & 31;
    const float* p = g_preds + (size_t)b*NLEADS*3 + c;

    const int l0 = lane, l1 = lane + 32;
    const bool v0 = l0 < NLEADS, v1 = l1 < NLEADS;
    float p0 = 1.f, p1 = 1.f, g0 = 0.f, g1 = 0.f, s = 0.f;
    if (v0) { p0 = p[l0*3]; g0 = log2f(1.0f - p0); s += g0; }
    if (v1) { p1 = p[l1*3]; g1 = log2f(1.0f - p1); s += g1; }
    #pragma unroll
    for (int o = 16; o; o >>= 1) s += __shfl_xor_sync(0xffffffffu, s, o);

    const float e = 2.0f / (float)(NLEADS - 1);
    float loss = 0.f;
    if (v0) loss += exp2f(e*(s - g0)) * logf(p0);
    if (v1) loss += exp2f(e*(s - g1)) * logf(p1);
    #pragma unroll
    for (int o = 16; o; o >>= 1) loss += __shfl_xor_sync(0xffffffffu, loss, o);
    if (lane == 0) out[b*3 + c] = -loss;
}

// no-ops BEFORE the main kernel so ncu's capture lands on lead_forward_kernel.
__global__ void noop_kernel() {}

extern "C" void kernel_launch(void* const* d_in, const int* in_sizes, int n_in,
                              void* d_out, int out_size)
{
    const float* x   = (const float*)d_in[0];
    const float* w1  = (const float*)d_in[1];
    const float* b1  = (const float*)d_in[2];
    const float* w2  = (const float*)d_in[3];
    const float* b2  = (const float*)d_in[4];
    const float* w3  = (const float*)d_in[5];
    const float* b3  = (const float*)d_in[6];
    const float* w4  = (const float*)d_in[7];
    const float* b4  = (const float*)d_in[8];
    const float* fcw = (const float*)d_in[9];
    const float* fcb = (const float*)d_in[10];
    float* out = (float*)d_out;

    cudaFuncSetAttribute(lead_forward_kernel,
                         cudaFuncAttributeMaxDynamicSharedMemorySize, SMEM_BYTES);

    noop_kernel<<<1, 32>>>();
    noop_kernel<<<1, 32>>>();
    noop_kernel<<<1, 32>>>();
    dim3 grid(NB, NLEADS);
    lead_forward_kernel<<<grid, 256, SMEM_BYTES>>>(x, w1, b1, w2, b2, w3, b3,
                                                   w4, b4, fcw, fcb);
    loss_kernel<<<NB, 96>>>(out);
}

// round 12
// speedup vs baseline: 1.2855x; 1.2855x over previous
#include <cuda_runtime.h>
#include <math.h>

#define NLEADS 61
#define NB 128
typedef unsigned long long ull;

__device__ float g_preds[NB * NLEADS * 3];

// ---------------- packed fp32x2 ops (Blackwell) ----------------
__device__ __forceinline__ ull ffma2(ull a, ull b, ull c) {
    ull d;
    asm("fma.rn.f32x2 %0, %1, %2, %3;" : "=l"(d) : "l"(a), "l"(b), "l"(c));
    return d;
}
__device__ __forceinline__ ull pk(float lo, float hi) {
    ull r;
    asm("mov.b64 %0, {%1, %2};" : "=l"(r) : "f"(lo), "f"(hi));
    return r;
}
__device__ __forceinline__ float2 upk(ull v) {
    float2 f;
    asm("mov.b64 {%0, %1}, %2;" : "=f"(f.x), "=f"(f.y) : "l"(v));
    return f;
}
__device__ __forceinline__ float hsum(ull v) {
    const float2 f = upk(v);
    return f.x + f.y;
}

// ---- shared memory layout (floats), total 13112 fl = 52.4 KB -> 4 CTAs/SM ----
#define OFF_A1P 0        // [8][18][68] = 9792 fl
#define OFF_W1D 9792     // 192 fl (dup pairs)
#define OFF_W2D 9984     // 3072 fl (dup pairs)
#define OFF_B1  13056    // 8
#define OFF_B2  13064    // 16
#define OFF_B3  13080    // 32
#define SMEM_FLOATS 13112
#define SMEM_BYTES (SMEM_FLOATS*4)   // 52448

// aliases inside the A1P region (valid after L2's read-complete sync)
#define OFF_W3  0        // 6144 fl (RAW w3; natural tap pairs)
#define OFF_A2P 6144     // [16][6][20] = 1920 fl (16B aligned)
#define OFF_A3  8064     // 256 fl (16B aligned)
#define OFF_A4  8320     // 64
#define OFF_LG  8384     // 4

__global__ void __launch_bounds__(256, 4)
lead_forward_kernel(const float* __restrict__ x,
                    const float* __restrict__ w1g, const float* __restrict__ b1g,
                    const float* __restrict__ w2g, const float* __restrict__ b2g,
                    const float* __restrict__ w3g, const float* __restrict__ b3g,
                    const float* __restrict__ w4g, const float* __restrict__ b4g,
                    const float* __restrict__ fcw, const float* __restrict__ fcb)
{
    extern __shared__ float sm[];
    float*  sA1p = sm + OFF_A1P;
    float4* A1p4 = (float4*)sA1p;
    float*  sA2p = sm + OFF_A2P;
    float*  sA3  = sm + OFF_A3;
    float*  sA4  = sm + OFF_A4;
    float*  sLg  = sm + OFF_LG;
    float*  sw1d = sm + OFF_W1D;
    float*  sw2d = sm + OFF_W2D;
    float*  sw3  = sm + OFF_W3;
    float*  sb1  = sm + OFF_B1;
    float*  sb2  = sm + OFF_B2;
    float*  sb3  = sm + OFF_B3;

    const int tid = threadIdx.x;
    const int b = blockIdx.x;
    const int l = blockIdx.y;
    const float4 z4 = make_float4(0.f,0.f,0.f,0.f);
    const float2 z2 = make_float2(0.f, 0.f);
    const float2* x2 = (const float2*)(x + ((size_t)(b*NLEADS + l))*8000);

    // ---- init: zero ONLY the A1p halo ----
    for (int i = tid; i < 8*2*17; i += 256) {
        const int pl = i / 34, sub = i % 34;
        const int row = (sub / 17) * 17;          // 0 or 17
        A1p4[pl*306 + row*17 + (sub % 17)] = z4;
    }
    if (tid < 128) {
        const int pl = tid >> 4, r = (tid & 15) + 1;
        sA1p[pl*1224 + r*68] = 0.0f;
        A1p4[pl*306 + r*17 + 16] = z4;
    }
    // ---- stage dup weight pairs + biases ----
    if (tid < 96) {
        const float v = w1g[l*96 + tid];
        ((float2*)sw1d)[tid] = make_float2(v, v);
    }
    #pragma unroll
    for (int k = 0; k < 6; k++) {
        const int i = tid + k*256;
        if (i < 1536) {
            const float v = w2g[l*1536 + i];
            ((float2*)sw2d)[i] = make_float2(v, v);
        }
    }
    if (tid < 8)  sb1[tid] = b1g[l*8 + tid];
    if (tid < 16) sb2[tid] = b2g[l*16 + tid];
    if (tid < 32) sb3[tid] = b3g[l*32 + tid];
    __syncthreads();

    // =====================================================================
    // Layer 1 (pooled-row PAIRS): conv (1->8, 3x4, s(1,2), pad (1,1)(2,2))
    // + pool + relu -> pooled (8,16,63) into A1p. Direct global-x patches.
    // Predicated loads (R10 form — NO branch: divergence costs more).
    // =====================================================================
    for (int pair = tid; pair < 8*63; pair += 256) {
        const int pp = pair / 63, pw = pair - pp*63;
        ull P[6][4];
        #pragma unroll
        for (int r = 0; r < 6; r++) {
            const int sr = 4*pp - 1 + r;                 // x row
            const bool rv = (sr >= 0) & (sr < 32);
            const float2* rp = x2 + sr*125 + (2*pw - 1);
            const float2 pA = (rv && pw > 0)  ? rp[0] : z2;
            const float2 pB =  rv             ? rp[1] : z2;
            const float2 pC = (rv && pw < 62) ? rp[2] : z2;
            P[r][0] = pk(pA.x, pB.x);
            P[r][1] = pk(pA.y, pB.y);
            P[r][2] = pk(pB.x, pC.x);
            P[r][3] = pk(pB.y, pC.y);
        }
        #pragma unroll
        for (int co = 0; co < 8; co++) {
            const ulonglong2* wq = (const ulonglong2*)(sw1d + co*24);
            ull a0=0ull, a1=0ull, a2=0ull, a3=0ull;
            #pragma unroll
            for (int j = 0; j < 6; j++) {
                const ulonglong2 q = wq[j];
                {   const int t = 2*j, kh = t>>2, kw = t&3;
                    a0 = ffma2(P[kh+0][kw], q.x, a0);
                    a1 = ffma2(P[kh+1][kw], q.x, a1);
                    a2 = ffma2(P[kh+2][kw], q.x, a2);
                    a3 = ffma2(P[kh+3][kw], q.x, a3); }
                {   const int t = 2*j+1, kh = t>>2, kw = t&3;
                    a0 = ffma2(P[kh+0][kw], q.y, a0);
                    a1 = ffma2(P[kh+1][kw], q.y, a1);
                    a2 = ffma2(P[kh+2][kw], q.y, a2);
                    a3 = ffma2(P[kh+3][kw], q.y, a3); }
            }
            const float bias = sb1[co];
            const float2 f0 = upk(a0), f1 = upk(a1), f2 = upk(a2), f3 = upk(a3);
            const float m0 = fmaxf(fmaxf(f0.x, f0.y), fmaxf(f1.x, f1.y)) + bias;
            const float m1 = fmaxf(fmaxf(f2.x, f2.y), fmaxf(f3.x, f3.y)) + bias;
            sA1p[co*(18*68) + (2*pp+1)*68 + (pw+1)] = fmaxf(m0, 0.0f);
            sA1p[co*(18*68) + (2*pp+2)*68 + (pw+1)] = fmaxf(m1, 0.0f);
        }
    }
    __syncthreads();

    // =====================================================================
    // Layer 2 (R8 mapping): conv (8->16, 4x3, s(2,2), pad 1) + pool + relu
    // (8,16,63) -> pooled (16,4,16). thread = (cg of 4 co) x (64 pos).
    // =====================================================================
    {
        const int pos = tid & 63;
        const int cg  = tid >> 6;
        const int ph = pos >> 4, pw = pos & 15;
        ull a0[4], a1[4];
        #pragma unroll
        for (int i = 0; i < 4; i++) { a0[i] = 0ull; a1[i] = 0ull; }

        #pragma unroll 1
        for (int ci = 0; ci < 8; ci++) {
            ull P[6][3];
            #pragma unroll
            for (int r = 0; r < 6; r++) {
                const int sr = 4*ph + r;
                const float4 v = A1p4[ci*(18*17) + sr*17 + pw];
                const float  e = sA1p[ci*(18*68) + sr*68 + 4*pw + 4];
                P[r][0] = pk(v.x, v.z);
                P[r][1] = pk(v.y, v.w);
                P[r][2] = pk(v.z, e);
            }
            #pragma unroll
            for (int i = 0; i < 4; i++) {
                const int co = cg*4 + i;
                const ulonglong2* wq = (const ulonglong2*)(sw2d + (co*8 + ci)*24);
                #pragma unroll
                for (int j = 0; j < 6; j++) {
                    const ulonglong2 q = wq[j];
                    const int t0 = 2*j, t1 = 2*j + 1;
                    a0[i] = ffma2(P[t0/3][t0%3],     q.x, a0[i]);
                    a1[i] = ffma2(P[t0/3 + 2][t0%3], q.x, a1[i]);
                    a0[i] = ffma2(P[t1/3][t1%3],     q.y, a0[i]);
                    a1[i] = ffma2(P[t1/3 + 2][t1%3], q.y, a1[i]);
                }
            }
        }
        __syncthreads();   // ALL A1p reads done -> safe to overwrite region
        #pragma unroll
        for (int i = 0; i < 4; i++) {
            const int co = cg*4 + i;
            const float2 f0 = upk(a0[i]), f1 = upk(a1[i]);
            const float m = fmaxf(fmaxf(f0.x, f0.y), fmaxf(f1.x, f1.y)) + sb2[co];
            sA2p[co*(6*20) + (ph+1)*20 + (pw+1)] = fmaxf(m, 0.0f);
        }
        // zero A2p halo (rows 0,5 and cols 0,17..19 of each [6][20] plane)
        for (int i = tid; i < 16*20; i += 256) {
            const int ci2 = i / 20, c = i % 20;
            sA2p[ci2*120 + 0*20 + c]  = 0.0f;
            sA2p[ci2*120 + 5*20 + c]  = 0.0f;
        }
        for (int i = tid; i < 16*4; i += 256) {
            const int ci2 = i / 4, r = (i & 3) + 1;
            float* row = sA2p + ci2*120 + r*20;
            row[0] = 0.0f; row[17] = 0.0f; row[18] = 0.0f; row[19] = 0.0f;
        }
    }
    // stage RAW w3 into freed A1p head (coalesced float4)
    {
        const float4* w34 = (const float4*)(w3g + (size_t)l*6144);
        #pragma unroll
        for (int k = 0; k < 6; k++) ((float4*)sw3)[tid + k*256] = w34[tid + k*256];
    }
    __syncthreads();

    // =====================================================================
    // Layer 3 (TAP-PAIRED): conv (16->32, 3x4, s(1,2), pad 1) + pool + relu
    // (16,4,16) -> pooled (32,2,4). thread = (co-pair of 16) x (8 pos).
    // =====================================================================
    if (tid < 128) {
        const int cp  = tid >> 3;
        const int pos = tid & 7;
        const int ph = pos >> 2, pw = pos & 3;
        ull vA0[2], vA1[2], vB0[2], vB1[2];
        #pragma unroll
        for (int c = 0; c < 2; c++) { vA0[c]=vA1[c]=vB0[c]=vB1[c]=0ull; }

        #pragma unroll 1
        for (int ci = 0; ci < 16; ci++) {
            ull p0[4], p1[4], p2[4];
            #pragma unroll
            for (int r = 0; r < 4; r++) {
                const int base = ci*120 + (2*ph + r)*20 + 4*pw;
                const ulonglong2 q = *(const ulonglong2*)(sA2p + base);
                p0[r] = q.x; p1[r] = q.y;
                p2[r] = *(const ull*)(sA2p + base + 4);
            }
            #pragma unroll
            for (int c = 0; c < 2; c++) {
                const int co = cp*2 + c;
                const ulonglong2* wq = (const ulonglong2*)(sw3 + (co*16 + ci)*12);
                const ulonglong2 q0 = wq[0];
                const ulonglong2 q1 = wq[1];
                const ulonglong2 q2 = wq[2];
                vA0[c] = ffma2(p0[0], q0.x, vA0[c]); vA0[c] = ffma2(p1[0], q0.y, vA0[c]);
                vA0[c] = ffma2(p0[1], q1.x, vA0[c]); vA0[c] = ffma2(p1[1], q1.y, vA0[c]);
                vA0[c] = ffma2(p0[2], q2.x, vA0[c]); vA0[c] = ffma2(p1[2], q2.y, vA0[c]);

                vA1[c] = ffma2(p0[1], q0.x, vA1[c]); vA1[c] = ffma2(p1[1], q0.y, vA1[c]);
                vA1[c] = ffma2(p0[2], q1.x, vA1[c]); vA1[c] = ffma2(p1[2], q1.y, vA1[c]);
                vA1[c] = ffma2(p0[3], q2.x, vA1[c]); vA1[c] = ffma2(p1[3], q2.y, vA1[c]);

                vB0[c] = ffma2(p1[0], q0.x, vB0[c]); vB0[c] = ffma2(p2[0], q0.y, vB0[c]);
                vB0[c] = ffma2(p1[1], q1.x, vB0[c]); vB0[c] = ffma2(p2[1], q1.y, vB0[c]);
                vB0[c] = ffma2(p1[2], q2.x, vB0[c]); vB0[c] = ffma2(p2[2], q2.y, vB0[c]);

                vB1[c] = ffma2(p1[1], q0.x, vB1[c]); vB1[c] = ffma2(p2[1], q0.y, vB1[c]);
                vB1[c] = ffma2(p1[2], q1.x, vB1[c]); vB1[c] = ffma2(p2[2], q1.y, vB1[c]);
                vB1[c] = ffma2(p1[3], q2.x, vB1[c]); vB1[c] = ffma2(p2[3], q2.y, vB1[c]);
            }
        }
        #pragma unroll
        for (int c = 0; c < 2; c++) {
            const int co = cp*2 + c;
            const float a0 = hsum(vA0[c]), a1 = hsum(vA1[c]);
            const float b0 = hsum(vB0[c]), b1 = hsum(vB1[c]);
            const float m = fmaxf(fmaxf(a0, b0), fmaxf(a1, b1)) + sb3[co];
            sA3[co*8 + pos] = fmaxf(m, 0.0f);
        }
    }
    __syncthreads();

    // =====================================================================
    // Layer 4 (R10 mapping, ull loads): dot(256) per co; warp-per-8co,
    // lane-coalesced ulonglong2 loads (same addresses as R10's float4 —
    // identical coalescing — but zero pk MOVs).
    // =====================================================================
    {
        const int warp = tid >> 5, lane = tid & 31;
        const ulonglong2* a3q = (const ulonglong2*)sA3;      // 64 entries
        const ulonglong2 av0 = a3q[lane], av1 = a3q[lane + 32];
        #pragma unroll 1
        for (int j = 0; j < 8; j++) {
            const int co = warp*8 + j;
            const ulonglong2* wr = (const ulonglong2*)(w4g + ((size_t)(l*64 + co))*256);
            const ulonglong2 w0 = wr[lane], w1 = wr[lane + 32];
            ull acc = ffma2(w0.x, av0.x, 0ull);
            acc = ffma2(w0.y, av0.y, acc);
            acc = ffma2(w1.x, av1.x, acc);
            acc = ffma2(w1.y, av1.y, acc);
            float s = hsum(acc);
            #pragma unroll
            for (int o = 16; o; o >>= 1) s += __shfl_xor_sync(0xffffffffu, s, o);
            if (lane == 0) sA4[co] = s + b4g[l*64 + co];
        }
    }
    __syncthreads();

    // ---- FC (64->3): one warp per class ----
    if (tid < 96) {
        const int c = tid >> 5, lane = tid & 31;
        const float* w = fcw + ((size_t)(l*3 + c))*64;
        float a = w[lane]*sA4[lane] + w[lane+32]*sA4[lane+32];
        #pragma unroll
        for (int o = 16; o; o >>= 1) a += __shfl_xor_sync(0xffffffffu, a, o);
        if (lane == 0) sLg[c] = a + fcb[l*3 + c];
    }
    __syncthreads();

    // ---- softmax, one thread ----
    if (tid == 0) {
        const float m = fmaxf(sLg[0], fmaxf(sLg[1], sLg[2]));
        const float e0 = expf(sLg[0]-m), e1 = expf(sLg[1]-m), e2 = expf(sLg[2]-m);
        const float inv = 1.0f / (e0 + e1 + e2);
        float* outp = g_preds + ((size_t)(b*NLEADS + l))*3;
        outp[0] = e0*inv; outp[1] = e1*inv; outp[2] = e2*inv;
    }
}

// =====================================================================
// Fusion loss in log2 space. One block per batch, one warp per class.
// =====================================================================
__global__ void loss_kernel(float* __restrict__ out)
{
    const int b = blockIdx.x;
    const int c = threadIdx.x >> 5;
    const int lane = threadIdx.x & 31;
    const float* p = g_preds + (size_t)b*NLEADS*3 + c;

    const int l0 = lane, l1 = lane + 32;
    const bool v0 = l0 < NLEADS, v1 = l1 < NLEADS;
    float p0 = 1.f, p1 = 1.f, g0 = 0.f, g1 = 0.f, s = 0.f;
    if (v0) { p0 = p[l0*3]; g0 = log2f(1.0f - p0); s += g0; }
    if (v1) { p1 = p[l1*3]; g1 = log2f(1.0f - p1); s += g1; }
    #pragma unroll
    for (int o = 16; o; o >>= 1) s += __shfl_xor_sync(0xffffffffu, s, o);

    const float e = 2.0f / (float)(NLEADS - 1);
    float loss = 0.f;
    if (v0) loss += exp2f(e*(s - g0)) * logf(p0);
    if (v1) loss += exp2f(e*(s - g1)) * logf(p1);
    #pragma unroll
    for (int o = 16; o; o >>= 1) loss += __shfl_xor_sync(0xffffffffu, loss, o);
    if (lane == 0) out[b*3 + c] = -loss;
}

// no-ops BEFORE the main kernel so ncu's capture lands on lead_forward_kernel.
__global__ void noop_kernel() {}

extern "C" void kernel_launch(void* const* d_in, const int* in_sizes, int n_in,
                              void* d_out, int out_size)
{
    const float* x   = (const float*)d_in[0];
    const float* w1  = (const float*)d_in[1];
    const float* b1  = (const float*)d_in[2];
    const float* w2  = (const float*)d_in[3];
    const float* b2  = (const float*)d_in[4];
    const float* w3  = (const float*)d_in[5];
    const float* b3  = (const float*)d_in[6];
    const float* w4  = (const float*)d_in[7];
    const float* b4  = (const float*)d_in[8];
    const float* fcw = (const float*)d_in[9];
    const float* fcb = (const float*)d_in[10];
    float* out = (float*)d_out;

    cudaFuncSetAttribute(lead_forward_kernel,
                         cudaFuncAttributeMaxDynamicSharedMemorySize, SMEM_BYTES);

    noop_kernel<<<1, 32>>>();
    noop_kernel<<<1, 32>>>();
    noop_kernel<<<1, 32>>>();
    dim3 grid(NB, NLEADS);
    lead_forward_kernel<<<grid, 256, SMEM_BYTES>>>(x, w1, b1, w2, b2, w3, b3,
                                                   w4, b4, fcw, fcb);
    loss_kernel<<<NB, 96>>>(out);
}

// round 13
// speedup vs baseline: 1.3050x; 1.0152x over previous
#include <cuda_runtime.h>
#include <math.h>

#define NLEADS 61
#define NB 128
typedef unsigned long long ull;

__device__ float g_preds[NB * NLEADS * 3];
// folded FC: W_eff[l][3][256] = fcw[l] @ w4[l];  b_eff[l][3] = fcw@b4 + fcb
__device__ float g_weff[NLEADS * 3 * 256];
__device__ float g_beff[NLEADS * 3];

// ---------------- packed fp32x2 ops (Blackwell) ----------------
__device__ __forceinline__ ull ffma2(ull a, ull b, ull c) {
    ull d;
    asm("fma.rn.f32x2 %0, %1, %2, %3;" : "=l"(d) : "l"(a), "l"(b), "l"(c));
    return d;
}
__device__ __forceinline__ ull pk(float lo, float hi) {
    ull r;
    asm("mov.b64 %0, {%1, %2};" : "=l"(r) : "f"(lo), "f"(hi));
    return r;
}
__device__ __forceinline__ float2 upk(ull v) {
    float2 f;
    asm("mov.b64 {%0, %1}, %2;" : "=f"(f.x), "=f"(f.y) : "l"(v));
    return f;
}
__device__ __forceinline__ float hsum(ull v) {
    const float2 f = upk(v);
    return f.x + f.y;
}

// ---- shared memory layout (floats), total 13112 fl = 52.4 KB -> 4 CTAs/SM ----
#define OFF_A1P 0        // [8][18][68] = 9792 fl
#define OFF_W1D 9792     // 192 fl (dup pairs)
#define OFF_W2D 9984     // 3072 fl (dup pairs)
#define OFF_B1  13056    // 8
#define OFF_B2  13064    // 16
#define OFF_B3  13080    // 32
#define SMEM_FLOATS 13112
#define SMEM_BYTES (SMEM_FLOATS*4)   // 52448

// aliases inside the A1P region (valid after L2's read-complete sync)
#define OFF_W3  0        // 6144 fl (RAW w3; natural tap pairs)
#define OFF_A2P 6144     // [16][6][20] = 1920 fl (16B aligned)
#define OFF_A3  8064     // 256 fl (16B aligned)
#define OFF_LG  8320     // 4

__global__ void __launch_bounds__(256, 4)
lead_forward_kernel(const float* __restrict__ x,
                    const float* __restrict__ w1g, const float* __restrict__ b1g,
                    const float* __restrict__ w2g, const float* __restrict__ b2g,
                    const float* __restrict__ w3g, const float* __restrict__ b3g,
                    const float* __restrict__ w4g, const float* __restrict__ b4g,
                    const float* __restrict__ fcw, const float* __restrict__ fcb)
{
    extern __shared__ float sm[];
    float*  sA1p = sm + OFF_A1P;
    float4* A1p4 = (float4*)sA1p;
    float*  sA2p = sm + OFF_A2P;
    float*  sA3  = sm + OFF_A3;
    float*  sLg  = sm + OFF_LG;
    float*  sw1d = sm + OFF_W1D;
    float*  sw2d = sm + OFF_W2D;
    float*  sw3  = sm + OFF_W3;
    float*  sb1  = sm + OFF_B1;
    float*  sb2  = sm + OFF_B2;
    float*  sb3  = sm + OFF_B3;

    const int tid = threadIdx.x;
    const int b = blockIdx.x;
    const int l = blockIdx.y;
    const float4 z4 = make_float4(0.f,0.f,0.f,0.f);
    const float2 z2 = make_float2(0.f, 0.f);
    const float2* x2 = (const float2*)(x + ((size_t)(b*NLEADS + l))*8000);

    // ---- init: zero ONLY the A1p halo ----
    for (int i = tid; i < 8*2*17; i += 256) {
        const int pl = i / 34, sub = i % 34;
        const int row = (sub / 17) * 17;          // 0 or 17
        A1p4[pl*306 + row*17 + (sub % 17)] = z4;
    }
    if (tid < 128) {
        const int pl = tid >> 4, r = (tid & 15) + 1;
        sA1p[pl*1224 + r*68] = 0.0f;
        A1p4[pl*306 + r*17 + 16] = z4;
    }
    // ---- stage dup weight pairs + biases ----
    if (tid < 96) {
        const float v = w1g[l*96 + tid];
        ((float2*)sw1d)[tid] = make_float2(v, v);
    }
    #pragma unroll
    for (int k = 0; k < 6; k++) {
        const int i = tid + k*256;
        if (i < 1536) {
            const float v = w2g[l*1536 + i];
            ((float2*)sw2d)[i] = make_float2(v, v);
        }
    }
    if (tid < 8)  sb1[tid] = b1g[l*8 + tid];
    if (tid < 16) sb2[tid] = b2g[l*16 + tid];
    if (tid < 32) sb3[tid] = b3g[l*32 + tid];
    __syncthreads();

    // =====================================================================
    // Layer 1 (pooled-row PAIRS): conv (1->8, 3x4, s(1,2), pad (1,1)(2,2))
    // + pool + relu -> pooled (8,16,63) into A1p. Direct global-x patches.
    // =====================================================================
    for (int pair = tid; pair < 8*63; pair += 256) {
        const int pp = pair / 63, pw = pair - pp*63;
        ull P[6][4];
        #pragma unroll
        for (int r = 0; r < 6; r++) {
            const int sr = 4*pp - 1 + r;                 // x row
            const bool rv = (sr >= 0) & (sr < 32);
            const float2* rp = x2 + sr*125 + (2*pw - 1);
            const float2 pA = (rv && pw > 0)  ? rp[0] : z2;
            const float2 pB =  rv             ? rp[1] : z2;
            const float2 pC = (rv && pw < 62) ? rp[2] : z2;
            P[r][0] = pk(pA.x, pB.x);
            P[r][1] = pk(pA.y, pB.y);
            P[r][2] = pk(pB.x, pC.x);
            P[r][3] = pk(pB.y, pC.y);
        }
        #pragma unroll
        for (int co = 0; co < 8; co++) {
            const ulonglong2* wq = (const ulonglong2*)(sw1d + co*24);
            ull a0=0ull, a1=0ull, a2=0ull, a3=0ull;
            #pragma unroll
            for (int j = 0; j < 6; j++) {
                const ulonglong2 q = wq[j];
                {   const int t = 2*j, kh = t>>2, kw = t&3;
                    a0 = ffma2(P[kh+0][kw], q.x, a0);
                    a1 = ffma2(P[kh+1][kw], q.x, a1);
                    a2 = ffma2(P[kh+2][kw], q.x, a2);
                    a3 = ffma2(P[kh+3][kw], q.x, a3); }
                {   const int t = 2*j+1, kh = t>>2, kw = t&3;
                    a0 = ffma2(P[kh+0][kw], q.y, a0);
                    a1 = ffma2(P[kh+1][kw], q.y, a1);
                    a2 = ffma2(P[kh+2][kw], q.y, a2);
                    a3 = ffma2(P[kh+3][kw], q.y, a3); }
            }
            const float bias = sb1[co];
            const float2 f0 = upk(a0), f1 = upk(a1), f2 = upk(a2), f3 = upk(a3);
            const float m0 = fmaxf(fmaxf(f0.x, f0.y), fmaxf(f1.x, f1.y)) + bias;
            const float m1 = fmaxf(fmaxf(f2.x, f2.y), fmaxf(f3.x, f3.y)) + bias;
            sA1p[co*(18*68) + (2*pp+1)*68 + (pw+1)] = fmaxf(m0, 0.0f);
            sA1p[co*(18*68) + (2*pp+2)*68 + (pw+1)] = fmaxf(m1, 0.0f);
        }
    }
    __syncthreads();

    // =====================================================================
    // Layer 2 (R8 mapping): conv (8->16, 4x3, s(2,2), pad 1) + pool + relu
    // (8,16,63) -> pooled (16,4,16). thread = (cg of 4 co) x (64 pos).
    // =====================================================================
    {
        const int pos = tid & 63;
        const int cg  = tid >> 6;
        const int ph = pos >> 4, pw = pos & 15;
        ull a0[4], a1[4];
        #pragma unroll
        for (int i = 0; i < 4; i++) { a0[i] = 0ull; a1[i] = 0ull; }

        #pragma unroll 1
        for (int ci = 0; ci < 8; ci++) {
            ull P[6][3];
            #pragma unroll
            for (int r = 0; r < 6; r++) {
                const int sr = 4*ph + r;
                const float4 v = A1p4[ci*(18*17) + sr*17 + pw];
                const float  e = sA1p[ci*(18*68) + sr*68 + 4*pw + 4];
                P[r][0] = pk(v.x, v.z);
                P[r][1] = pk(v.y, v.w);
                P[r][2] = pk(v.z, e);
            }
            #pragma unroll
            for (int i = 0; i < 4; i++) {
                const int co = cg*4 + i;
                const ulonglong2* wq = (const ulonglong2*)(sw2d + (co*8 + ci)*24);
                #pragma unroll
                for (int j = 0; j < 6; j++) {
                    const ulonglong2 q = wq[j];
                    const int t0 = 2*j, t1 = 2*j + 1;
                    a0[i] = ffma2(P[t0/3][t0%3],     q.x, a0[i]);
                    a1[i] = ffma2(P[t0/3 + 2][t0%3], q.x, a1[i]);
                    a0[i] = ffma2(P[t1/3][t1%3],     q.y, a0[i]);
                    a1[i] = ffma2(P[t1/3 + 2][t1%3], q.y, a1[i]);
                }
            }
        }
        __syncthreads();   // ALL A1p reads done -> safe to overwrite region
        #pragma unroll
        for (int i = 0; i < 4; i++) {
            const int co = cg*4 + i;
            const float2 f0 = upk(a0[i]), f1 = upk(a1[i]);
            const float m = fmaxf(fmaxf(f0.x, f0.y), fmaxf(f1.x, f1.y)) + sb2[co];
            sA2p[co*(6*20) + (ph+1)*20 + (pw+1)] = fmaxf(m, 0.0f);
        }
        // zero A2p halo (rows 0,5 and cols 0,17..19 of each [6][20] plane)
        for (int i = tid; i < 16*20; i += 256) {
            const int ci2 = i / 20, c = i % 20;
            sA2p[ci2*120 + 0*20 + c]  = 0.0f;
            sA2p[ci2*120 + 5*20 + c]  = 0.0f;
        }
        for (int i = tid; i < 16*4; i += 256) {
            const int ci2 = i / 4, r = (i & 3) + 1;
            float* row = sA2p + ci2*120 + r*20;
            row[0] = 0.0f; row[17] = 0.0f; row[18] = 0.0f; row[19] = 0.0f;
        }
    }
    // stage RAW w3 into freed A1p head (coalesced float4)
    {
        const float4* w34 = (const float4*)(w3g + (size_t)l*6144);
        #pragma unroll
        for (int k = 0; k < 6; k++) ((float4*)sw3)[tid + k*256] = w34[tid + k*256];
    }
    __syncthreads();

    // =====================================================================
    // Layer 3 (TAP-PAIRED): conv (16->32, 3x4, s(1,2), pad 1) + pool + relu
    // (16,4,16) -> pooled (32,2,4). thread = (co-pair of 16) x (8 pos).
    // =====================================================================
    if (tid < 128) {
        const int cp  = tid >> 3;
        const int pos = tid & 7;
        const int ph = pos >> 2, pw = pos & 3;
        ull vA0[2], vA1[2], vB0[2], vB1[2];
        #pragma unroll
        for (int c = 0; c < 2; c++) { vA0[c]=vA1[c]=vB0[c]=vB1[c]=0ull; }

        #pragma unroll 1
        for (int ci = 0; ci < 16; ci++) {
            ull p0[4], p1[4], p2[4];
            #pragma unroll
            for (int r = 0; r < 4; r++) {
                const int base = ci*120 + (2*ph + r)*20 + 4*pw;
                const ulonglong2 q = *(const ulonglong2*)(sA2p + base);
                p0[r] = q.x; p1[r] = q.y;
                p2[r] = *(const ull*)(sA2p + base + 4);
            }
            #pragma unroll
            for (int c = 0; c < 2; c++) {
                const int co = cp*2 + c;
                const ulonglong2* wq = (const ulonglong2*)(sw3 + (co*16 + ci)*12);
                const ulonglong2 q0 = wq[0];
                const ulonglong2 q1 = wq[1];
                const ulonglong2 q2 = wq[2];
                vA0[c] = ffma2(p0[0], q0.x, vA0[c]); vA0[c] = ffma2(p1[0], q0.y, vA0[c]);
                vA0[c] = ffma2(p0[1], q1.x, vA0[c]); vA0[c] = ffma2(p1[1], q1.y, vA0[c]);
                vA0[c] = ffma2(p0[2], q2.x, vA0[c]); vA0[c] = ffma2(p1[2], q2.y, vA0[c]);

                vA1[c] = ffma2(p0[1], q0.x, vA1[c]); vA1[c] = ffma2(p1[1], q0.y, vA1[c]);
                vA1[c] = ffma2(p0[2], q1.x, vA1[c]); vA1[c] = ffma2(p1[2], q1.y, vA1[c]);
                vA1[c] = ffma2(p0[3], q2.x, vA1[c]); vA1[c] = ffma2(p1[3], q2.y, vA1[c]);

                vB0[c] = ffma2(p1[0], q0.x, vB0[c]); vB0[c] = ffma2(p2[0], q0.y, vB0[c]);
                vB0[c] = ffma2(p1[1], q1.x, vB0[c]); vB0[c] = ffma2(p2[1], q1.y, vB0[c]);
                vB0[c] = ffma2(p1[2], q2.x, vB0[c]); vB0[c] = ffma2(p2[2], q2.y, vB0[c]);

                vB1[c] = ffma2(p1[1], q0.x, vB1[c]); vB1[c] = ffma2(p2[1], q0.y, vB1[c]);
                vB1[c] = ffma2(p1[2], q1.x, vB1[c]); vB1[c] = ffma2(p2[2], q1.y, vB1[c]);
                vB1[c] = ffma2(p1[3], q2.x, vB1[c]); vB1[c] = ffma2(p2[3], q2.y, vB1[c]);
            }
        }
        #pragma unroll
        for (int c = 0; c < 2; c++) {
            const int co = cp*2 + c;
            const float a0 = hsum(vA0[c]), a1 = hsum(vA1[c]);
            const float b0 = hsum(vB0[c]), b1 = hsum(vB1[c]);
            const float m = fmaxf(fmaxf(a0, b0), fmaxf(a1, b1)) + sb3[co];
            sA3[co*8 + pos] = fmaxf(m, 0.0f);
        }
    }
    __syncthreads();

    // =====================================================================
    // Folded L4+FC: logits[c] = W_eff[l][c] . a3 + b_eff[l][c]
    // (exact algebra: no relu after conv4 in the reference).
    // 3 warps; lane covers 8 contiguous floats via 2x LDG.128 / LDS.128.
    // =====================================================================
    if (tid < 96) {
        const int c = tid >> 5, lane = tid & 31;
        const ulonglong2* wv = (const ulonglong2*)(g_weff + ((size_t)(l*3 + c))*256) + lane*2;
        const ulonglong2* av = (const ulonglong2*)sA3 + lane*2;
        const ulonglong2 w0 = wv[0], w1 = wv[1];
        const ulonglong2 v0 = av[0], v1 = av[1];
        ull acc = ffma2(w0.x, v0.x, 0ull);
        acc = ffma2(w0.y, v0.y, acc);
        acc = ffma2(w1.x, v1.x, acc);
        acc = ffma2(w1.y, v1.y, acc);
        float s = hsum(acc);
        #pragma unroll
        for (int o = 16; o; o >>= 1) s += __shfl_xor_sync(0xffffffffu, s, o);
        if (lane == 0) sLg[c] = s + g_beff[l*3 + c];
    }
    __syncthreads();

    // ---- softmax, one thread ----
    if (tid == 0) {
        const float m = fmaxf(sLg[0], fmaxf(sLg[1], sLg[2]));
        const float e0 = expf(sLg[0]-m), e1 = expf(sLg[1]-m), e2 = expf(sLg[2]-m);
        const float inv = 1.0f / (e0 + e1 + e2);
        float* outp = g_preds + ((size_t)(b*NLEADS + l))*3;
        outp[0] = e0*inv; outp[1] = e1*inv; outp[2] = e2*inv;
    }
}

// =====================================================================
// Fold kernel: per lead l, W_eff[c][k] = sum_co fcw[c,co]*w4[co,k];
// b_eff[c] = sum_co fcw[c,co]*b4[co] + fcb[c].  Grid 61 x 256 threads.
// =====================================================================
__global__ void fold_fc_kernel(const float* __restrict__ w4g,
                               const float* __restrict__ b4g,
                               const float* __restrict__ fcw,
                               const float* __restrict__ fcb)
{
    __shared__ float sfc[192];
    const int l = blockIdx.x;
    const int tid = threadIdx.x;
    if (tid < 192) sfc[tid] = fcw[l*192 + tid];
    __syncthreads();

    const float* w4l = w4g + (size_t)l*64*256;
    float acc0 = 0.f, acc1 = 0.f, acc2 = 0.f;
    #pragma unroll 4
    for (int co = 0; co < 64; co++) {
        const float v = w4l[co*256 + tid];   // coalesced across tid
        acc0 += sfc[co]       * v;
        acc1 += sfc[64 + co]  * v;
        acc2 += sfc[128 + co] * v;
    }
    g_weff[((size_t)l*3 + 0)*256 + tid] = acc0;
    g_weff[((size_t)l*3 + 1)*256 + tid] = acc1;
    g_weff[((size_t)l*3 + 2)*256 + tid] = acc2;

    if (tid < 3) {
        float a = fcb[l*3 + tid];
        for (int co = 0; co < 64; co++) a += sfc[tid*64 + co] * b4g[l*64 + co];
        g_beff[l*3 + tid] = a;
    }
}

// =====================================================================
// Fusion loss in log2 space. One block per batch, one warp per class.
// =====================================================================
__global__ void loss_kernel(float* __restrict__ out)
{
    const int b = blockIdx.x;
    const int c = threadIdx.x >> 5;
    const int lane = threadIdx.x & 31;
    const float* p = g_preds + (size_t)b*NLEADS*3 + c;

    const int l0 = lane, l1 = lane + 32;
    const bool v0 = l0 < NLEADS, v1 = l1 < NLEADS;
    float p0 = 1.f, p1 = 1.f, g0 = 0.f, g1 = 0.f, s = 0.f;
    if (v0) { p0 = p[l0*3]; g0 = log2f(1.0f - p0); s += g0; }
    if (v1) { p1 = p[l1*3]; g1 = log2f(1.0f - p1); s += g1; }
    #pragma unroll
    for (int o = 16; o; o >>= 1) s += __shfl_xor_sync(0xffffffffu, s, o);

    const float e = 2.0f / (float)(NLEADS - 1);
    float loss = 0.f;
    if (v0) loss += exp2f(e*(s - g0)) * logf(p0);
    if (v1) loss += exp2f(e*(s - g1)) * logf(p1);
    #pragma unroll
    for (int o = 16; o; o >>= 1) loss += __shfl_xor_sync(0xffffffffu, loss, o);
    if (lane == 0) out[b*3 + c] = -loss;
}

// no-ops keep lead_forward_kernel at ncu's relative launch index 3.
__global__ void noop_kernel() {}

extern "C" void kernel_launch(void* const* d_in, const int* in_sizes, int n_in,
                              void* d_out, int out_size)
{
    const float* x   = (const float*)d_in[0];
    const float* w1  = (const float*)d_in[1];
    const float* b1  = (const float*)d_in[2];
    const float* w2  = (const float*)d_in[3];
    const float* b2  = (const float*)d_in[4];
    const float* w3  = (const float*)d_in[5];
    const float* b3  = (const float*)d_in[6];
    const float* w4  = (const float*)d_in[7];
    const float* b4  = (const float*)d_in[8];
    const float* fcw = (const float*)d_in[9];
    const float* fcb = (const float*)d_in[10];
    float* out = (float*)d_out;

    cudaFuncSetAttribute(lead_forward_kernel,
                         cudaFuncAttributeMaxDynamicSharedMemorySize, SMEM_BYTES);

    noop_kernel<<<1, 32>>>();
    noop_kernel<<<1, 32>>>();
    fold_fc_kernel<<<NLEADS, 256>>>(w4, b4, fcw, fcb);   // launch idx 2
    dim3 grid(NB, NLEADS);
    lead_forward_kernel<<<grid, 256, SMEM_BYTES>>>(x, w1, b1, w2, b2, w3, b3,
                                                   w4, b4, fcw, fcb);  // idx 3
    loss_kernel<<<NB, 96>>>(out);
}

// round 14
// speedup vs baseline: 1.3318x; 1.0205x over previous
#include <cuda_runtime.h>
#include <math.h>

#define NLEADS 61
#define NB 128
typedef unsigned long long ull;

__device__ float g_preds[NB * NLEADS * 3];
// folded FC: W_eff[l][3][256] = fcw[l] @ w4[l];  b_eff[l][3] = fcw@b4 + fcb
__device__ float g_weff[NLEADS * 3 * 256];
__device__ float g_beff[NLEADS * 3];

// ---------------- packed fp32x2 ops (Blackwell) ----------------
__device__ __forceinline__ ull ffma2(ull a, ull b, ull c) {
    ull d;
    asm("fma.rn.f32x2 %0, %1, %2, %3;" : "=l"(d) : "l"(a), "l"(b), "l"(c));
    return d;
}
__device__ __forceinline__ ull pk(float lo, float hi) {
    ull r;
    asm("mov.b64 %0, {%1, %2};" : "=l"(r) : "f"(lo), "f"(hi));
    return r;
}
__device__ __forceinline__ float2 upk(ull v) {
    float2 f;
    asm("mov.b64 {%0, %1}, %2;" : "=f"(f.x), "=f"(f.y) : "l"(v));
    return f;
}
__device__ __forceinline__ float hsum(ull v) {
    const float2 f = upk(v);
    return f.x + f.y;
}

// ---- shared memory layout (floats), 13884 fl = 55.5 KB -> 4 CTAs/SM ----
// A1 stored SPLIT: even columns plane E [8][18][34] then odd plane O.
#define OFF_A1E 0        // 4896 fl
#define OFF_A1O 4896     // 4896 fl (A1 region total 9792)
#define OFF_W1D 9792     // 192 fl (dup pairs)
#define OFF_W2D 9984     // 3072 fl (dup pairs)
#define OFF_B1  13056    // 8
#define OFF_B2  13064    // 16
#define OFF_B3  13080    // 32
#define OFF_WEFF 13112   // 772 fl: W_eff (768) + b_eff (3) + pad
#define SMEM_FLOATS 13884
#define SMEM_BYTES (SMEM_FLOATS*4)   // 55536

// aliases inside the A1 region (valid after L2's read-complete sync)
#define OFF_W3  0        // 6144 fl (RAW w3; natural tap pairs)
#define OFF_A2P 6144     // [16][6][20] = 1920 fl (16B aligned)
#define OFF_A3  8064     // 256 fl (16B aligned)
#define OFF_LG  8320     // 4

__global__ void __launch_bounds__(256, 4)
lead_forward_kernel(const float* __restrict__ x,
                    const float* __restrict__ w1g, const float* __restrict__ b1g,
                    const float* __restrict__ w2g, const float* __restrict__ b2g,
                    const float* __restrict__ w3g, const float* __restrict__ b3g,
                    const float* __restrict__ w4g, const float* __restrict__ b4g,
                    const float* __restrict__ fcw, const float* __restrict__ fcb)
{
    extern __shared__ float sm[];
    float*  sA1E = sm + OFF_A1E;
    float*  sA1O = sm + OFF_A1O;
    float*  sA2p = sm + OFF_A2P;
    float*  sA3  = sm + OFF_A3;
    float*  sLg  = sm + OFF_LG;
    float*  sw1d = sm + OFF_W1D;
    float*  sw2d = sm + OFF_W2D;
    float*  sw3  = sm + OFF_W3;
    float*  sb1  = sm + OFF_B1;
    float*  sb2  = sm + OFF_B2;
    float*  sb3  = sm + OFF_B3;
    float*  swef = sm + OFF_WEFF;

    const int tid = threadIdx.x;
    const int b = blockIdx.x;
    const int l = blockIdx.y;
    const float2 z2 = make_float2(0.f, 0.f);
    const float2* x2 = (const float2*)(x + ((size_t)(b*NLEADS + l))*8000);

    // ---- init: zero ONLY the A1 halo (split layout) ----
    // rows 0 and 17 of every plane in BOTH arrays (34 fl = 17 float2 each)
    for (int i = tid; i < 8*2*17; i += 256) {
        const int pl = i / 34, sub = i % 34;
        const int row = (sub >= 17) ? 17 : 0;
        const int c2  = sub % 17;
        ((float2*)(sA1E + pl*612 + row*34))[c2] = z2;
        ((float2*)(sA1O + pl*612 + row*34))[c2] = z2;
    }
    // rows 1..16: E col 0 (orig col 0), E cols 32,33 (orig 64,66),
    //             O cols 32,33 (orig 65,67)
    if (tid < 128) {
        const int pl = tid >> 4, r = (tid & 15) + 1;
        sA1E[pl*612 + r*34] = 0.0f;
        ((float2*)(sA1E + pl*612 + r*34 + 32))[0] = z2;
        ((float2*)(sA1O + pl*612 + r*34 + 32))[0] = z2;
    }
    // ---- stage dup weight pairs + biases ----
    if (tid < 96) {
        const float v = w1g[l*96 + tid];
        ((float2*)sw1d)[tid] = make_float2(v, v);
    }
    #pragma unroll
    for (int k = 0; k < 6; k++) {
        const int i = tid + k*256;
        if (i < 1536) {
            const float v = w2g[l*1536 + i];
            ((float2*)sw2d)[i] = make_float2(v, v);
        }
    }
    if (tid < 8)  sb1[tid] = b1g[l*8 + tid];
    if (tid < 16) sb2[tid] = b2g[l*16 + tid];
    if (tid < 32) sb3[tid] = b3g[l*32 + tid];
    __syncthreads();

    // =====================================================================
    // Layer 1 (pooled-row PAIRS): conv (1->8, 3x4, s(1,2), pad (1,1)(2,2))
    // + pool + relu -> pooled (8,16,63) into split A1 (E/O by col parity).
    // =====================================================================
    for (int pair = tid; pair < 8*63; pair += 256) {
        const int pp = pair / 63, pw = pair - pp*63;
        ull P[6][4];
        #pragma unroll
        for (int r = 0; r < 6; r++) {
            const int sr = 4*pp - 1 + r;                 // x row
            const bool rv = (sr >= 0) & (sr < 32);
            const float2* rp = x2 + sr*125 + (2*pw - 1);
            const float2 pA = (rv && pw > 0)  ? rp[0] : z2;
            const float2 pB =  rv             ? rp[1] : z2;
            const float2 pC = (rv && pw < 62) ? rp[2] : z2;
            P[r][0] = pk(pA.x, pB.x);
            P[r][1] = pk(pA.y, pB.y);
            P[r][2] = pk(pB.x, pC.x);
            P[r][3] = pk(pB.y, pC.y);
        }
        // output stored col j = pw+1 -> E plane if j even else O plane
        const int j = pw + 1;
        float* outb = ((j & 1) ? (sA1O + ((j - 1) >> 1)) : (sA1E + (j >> 1)))
                      + (2*pp + 1)*34;
        #pragma unroll
        for (int co = 0; co < 8; co++) {
            const ulonglong2* wq = (const ulonglong2*)(sw1d + co*24);
            ull a0=0ull, a1=0ull, a2=0ull, a3=0ull;
            #pragma unroll
            for (int jj = 0; jj < 6; jj++) {
                const ulonglong2 q = wq[jj];
                {   const int t = 2*jj, kh = t>>2, kw = t&3;
                    a0 = ffma2(P[kh+0][kw], q.x, a0);
                    a1 = ffma2(P[kh+1][kw], q.x, a1);
                    a2 = ffma2(P[kh+2][kw], q.x, a2);
                    a3 = ffma2(P[kh+3][kw], q.x, a3); }
                {   const int t = 2*jj+1, kh = t>>2, kw = t&3;
                    a0 = ffma2(P[kh+0][kw], q.y, a0);
                    a1 = ffma2(P[kh+1][kw], q.y, a1);
                    a2 = ffma2(P[kh+2][kw], q.y, a2);
                    a3 = ffma2(P[kh+3][kw], q.y, a3); }
            }
            const float bias = sb1[co];
            const float2 f0 = upk(a0), f1 = upk(a1), f2 = upk(a2), f3 = upk(a3);
            const float m0 = fmaxf(fmaxf(f0.x, f0.y), fmaxf(f1.x, f1.y)) + bias;
            const float m1 = fmaxf(fmaxf(f2.x, f2.y), fmaxf(f3.x, f3.y)) + bias;
            outb[co*612]      = fmaxf(m0, 0.0f);
            outb[co*612 + 34] = fmaxf(m1, 0.0f);
        }
    }
    __syncthreads();

    // =====================================================================
    // Layer 2 (R8 mapping, SPLIT reads): conv (8->16, 4x3, s(2,2), pad 1)
    // + pool + relu. (8,16,63) -> pooled (16,4,16).
    // P[r][0] = (X0,X2) = ull load from E;  P[r][1] = (X1,X3) = ull from O;
    // P[r][2] = (X2,X4) = 1 pk.  (was 2 loads + 3 pk)
    // =====================================================================
    {
        const int pos = tid & 63;
        const int cg  = tid >> 6;
        const int ph = pos >> 4, pw = pos & 15;
        ull a0[4], a1[4];
        #pragma unroll
        for (int i = 0; i < 4; i++) { a0[i] = 0ull; a1[i] = 0ull; }

        #pragma unroll 1
        for (int ci = 0; ci < 8; ci++) {
            ull P[6][3];
            #pragma unroll
            for (int r = 0; r < 6; r++) {
                const int off = ci*612 + (4*ph + r)*34 + 2*pw;
                const ull pe = *(const ull*)(sA1E + off);      // (X0, X2)
                const ull po = *(const ull*)(sA1O + off);      // (X1, X3)
                const float x4 = sA1E[off + 2];                // X4 (orig 4pw+4)
                P[r][0] = pe;
                P[r][1] = po;
                P[r][2] = pk(upk(pe).y, x4);                   // (X2, X4)
            }
            #pragma unroll
            for (int i = 0; i < 4; i++) {
                const int co = cg*4 + i;
                const ulonglong2* wq = (const ulonglong2*)(sw2d + (co*8 + ci)*24);
                #pragma unroll
                for (int jj = 0; jj < 6; jj++) {
                    const ulonglong2 q = wq[jj];
                    const int t0 = 2*jj, t1 = 2*jj + 1;
                    a0[i] = ffma2(P[t0/3][t0%3],     q.x, a0[i]);
                    a1[i] = ffma2(P[t0/3 + 2][t0%3], q.x, a1[i]);
                    a0[i] = ffma2(P[t1/3][t1%3],     q.y, a0[i]);
                    a1[i] = ffma2(P[t1/3 + 2][t1%3], q.y, a1[i]);
                }
            }
        }
        __syncthreads();   // ALL A1 reads done -> safe to overwrite region
        #pragma unroll
        for (int i = 0; i < 4; i++) {
            const int co = cg*4 + i;
            const float2 f0 = upk(a0[i]), f1 = upk(a1[i]);
            const float m = fmaxf(fmaxf(f0.x, f0.y), fmaxf(f1.x, f1.y)) + sb2[co];
            sA2p[co*(6*20) + (ph+1)*20 + (pw+1)] = fmaxf(m, 0.0f);
        }
        // zero A2p halo (rows 0,5 and cols 0,17..19 of each [6][20] plane)
        for (int i = tid; i < 16*20; i += 256) {
            const int ci2 = i / 20, c = i % 20;
            sA2p[ci2*120 + 0*20 + c]  = 0.0f;
            sA2p[ci2*120 + 5*20 + c]  = 0.0f;
        }
        for (int i = tid; i < 16*4; i += 256) {
            const int ci2 = i / 4, r = (i & 3) + 1;
            float* row = sA2p + ci2*120 + r*20;
            row[0] = 0.0f; row[17] = 0.0f; row[18] = 0.0f; row[19] = 0.0f;
        }
    }
    // stage RAW w3 into freed A1 head (coalesced float4)
    {
        const float4* w34 = (const float4*)(w3g + (size_t)l*6144);
        #pragma unroll
        for (int k = 0; k < 6; k++) ((float4*)sw3)[tid + k*256] = w34[tid + k*256];
    }
    __syncthreads();

    // =====================================================================
    // Layer 3 (TAP-PAIRED, 128 threads) + W_eff prefetch (other 128 threads).
    // =====================================================================
    if (tid < 128) {
        const int cp  = tid >> 3;
        const int pos = tid & 7;
        const int ph = pos >> 2, pw = pos & 3;
        ull vA0[2], vA1[2], vB0[2], vB1[2];
        #pragma unroll
        for (int c = 0; c < 2; c++) { vA0[c]=vA1[c]=vB0[c]=vB1[c]=0ull; }

        #pragma unroll 1
        for (int ci = 0; ci < 16; ci++) {
            ull p0[4], p1[4], p2[4];
            #pragma unroll
            for (int r = 0; r < 4; r++) {
                const int base = ci*120 + (2*ph + r)*20 + 4*pw;
                const ulonglong2 q = *(const ulonglong2*)(sA2p + base);
                p0[r] = q.x; p1[r] = q.y;
                p2[r] = *(const ull*)(sA2p + base + 4);
            }
            #pragma unroll
            for (int c = 0; c < 2; c++) {
                const int co = cp*2 + c;
                const ulonglong2* wq = (const ulonglong2*)(sw3 + (co*16 + ci)*12);
                const ulonglong2 q0 = wq[0];
                const ulonglong2 q1 = wq[1];
                const ulonglong2 q2 = wq[2];
                vA0[c] = ffma2(p0[0], q0.x, vA0[c]); vA0[c] = ffma2(p1[0], q0.y, vA0[c]);
                vA0[c] = ffma2(p0[1], q1.x, vA0[c]); vA0[c] = ffma2(p1[1], q1.y, vA0[c]);
                vA0[c] = ffma2(p0[2], q2.x, vA0[c]); vA0[c] = ffma2(p1[2], q2.y, vA0[c]);

                vA1[c] = ffma2(p0[1], q0.x, vA1[c]); vA1[c] = ffma2(p1[1], q0.y, vA1[c]);
                vA1[c] = ffma2(p0[2], q1.x, vA1[c]); vA1[c] = ffma2(p1[2], q1.y, vA1[c]);
                vA1[c] = ffma2(p0[3], q2.x, vA1[c]); vA1[c] = ffma2(p1[3], q2.y, vA1[c]);

                vB0[c] = ffma2(p1[0], q0.x, vB0[c]); vB0[c] = ffma2(p2[0], q0.y, vB0[c]);
                vB0[c] = ffma2(p1[1], q1.x, vB0[c]); vB0[c] = ffma2(p2[1], q1.y, vB0[c]);
                vB0[c] = ffma2(p1[2], q2.x, vB0[c]); vB0[c] = ffma2(p2[2], q2.y, vB0[c]);

                vB1[c] = ffma2(p1[1], q0.x, vB1[c]); vB1[c] = ffma2(p2[1], q0.y, vB1[c]);
                vB1[c] = ffma2(p1[2], q1.x, vB1[c]); vB1[c] = ffma2(p2[2], q1.y, vB1[c]);
                vB1[c] = ffma2(p1[3], q2.x, vB1[c]); vB1[c] = ffma2(p2[3], q2.y, vB1[c]);
            }
        }
        #pragma unroll
        for (int c = 0; c < 2; c++) {
            const int co = cp*2 + c;
            const float a0 = hsum(vA0[c]), a1 = hsum(vA1[c]);
            const float b0 = hsum(vB0[c]), b1 = hsum(vB1[c]);
            const float m = fmaxf(fmaxf(a0, b0), fmaxf(a1, b1)) + sb3[co];
            sA3[co*8 + pos] = fmaxf(m, 0.0f);
        }
    } else {
        // idle half-block prefetches this lead's folded FC weights into smem
        const int i = tid - 128;    // 0..127
        const float4* weff4 = (const float4*)(g_weff + (size_t)l*768);
        float4* swef4 = (float4*)swef;
        #pragma unroll
        for (int k = 0; k < 2; k++) {
            const int idx = i + k*128;
            if (idx < 192) swef4[idx] = weff4[idx];
        }
        if (i < 3) swef[768 + i] = g_beff[l*3 + i];
    }
    __syncthreads();

    // =====================================================================
    // Folded L4+FC (smem-hot): logits[c] = W_eff[l][c] . a3 + b_eff[l][c]
    // =====================================================================
    if (tid < 96) {
        const int c = tid >> 5, lane = tid & 31;
        const ulonglong2* wv = (const ulonglong2*)(swef + c*256) + lane*2;
        const ulonglong2* av = (const ulonglong2*)sA3 + lane*2;
        const ulonglong2 w0 = wv[0], w1 = wv[1];
        const ulonglong2 v0 = av[0], v1 = av[1];
        ull acc = ffma2(w0.x, v0.x, 0ull);
        acc = ffma2(w0.y, v0.y, acc);
        acc = ffma2(w1.x, v1.x, acc);
        acc = ffma2(w1.y, v1.y, acc);
        float s = hsum(acc);
        #pragma unroll
        for (int o = 16; o; o >>= 1) s += __shfl_xor_sync(0xffffffffu, s, o);
        if (lane == 0) sLg[c] = s + swef[768 + c];
    }
    __syncthreads();

    // ---- softmax, one thread ----
    if (tid == 0) {
        const float m = fmaxf(sLg[0], fmaxf(sLg[1], sLg[2]));
        const float e0 = expf(sLg[0]-m), e1 = expf(sLg[1]-m), e2 = expf(sLg[2]-m);
        const float inv = 1.0f / (e0 + e1 + e2);
        float* outp = g_preds + ((size_t)(b*NLEADS + l))*3;
        outp[0] = e0*inv; outp[1] = e1*inv; outp[2] = e2*inv;
    }
}

// =====================================================================
// Fold kernel: per lead l, W_eff[c][k] = sum_co fcw[c,co]*w4[co,k];
// b_eff[c] = sum_co fcw[c,co]*b4[co] + fcb[c].  Grid 61 x 256 threads.
// =====================================================================
__global__ void fold_fc_kernel(const float* __restrict__ w4g,
                               const float* __restrict__ b4g,
                               const float* __restrict__ fcw,
                               const float* __restrict__ fcb)
{
    __shared__ float sfc[192];
    const int l = blockIdx.x;
    const int tid = threadIdx.x;
    if (tid < 192) sfc[tid] = fcw[l*192 + tid];
    __syncthreads();

    const float* w4l = w4g + (size_t)l*64*256;
    float acc0 = 0.f, acc1 = 0.f, acc2 = 0.f;
    #pragma unroll 4
    for (int co = 0; co < 64; co++) {
        const float v = w4l[co*256 + tid];   // coalesced across tid
        acc0 += sfc[co]       * v;
        acc1 += sfc[64 + co]  * v;
        acc2 += sfc[128 + co] * v;
    }
    g_weff[((size_t)l*3 + 0)*256 + tid] = acc0;
    g_weff[((size_t)l*3 + 1)*256 + tid] = acc1;
    g_weff[((size_t)l*3 + 2)*256 + tid] = acc2;

    if (tid < 3) {
        float a = fcb[l*3 + tid];
        for (int co = 0; co < 64; co++) a += sfc[tid*64 + co] * b4g[l*64 + co];
        g_beff[l*3 + tid] = a;
    }
}

// =====================================================================
// Fusion loss in log2 space. One block per batch, one warp per class.
// =====================================================================
__global__ void loss_kernel(float* __restrict__ out)
{
    const int b = blockIdx.x;
    const int c = threadIdx.x >> 5;
    const int lane = threadIdx.x & 31;
    const float* p = g_preds + (size_t)b*NLEADS*3 + c;

    const int l0 = lane, l1 = lane + 32;
    const bool v0 = l0 < NLEADS, v1 = l1 < NLEADS;
    float p0 = 1.f, p1 = 1.f, g0 = 0.f, g1 = 0.f, s = 0.f;
    if (v0) { p0 = p[l0*3]; g0 = log2f(1.0f - p0); s += g0; }
    if (v1) { p1 = p[l1*3]; g1 = log2f(1.0f - p1); s += g1; }
    #pragma unroll
    for (int o = 16; o; o >>= 1) s += __shfl_xor_sync(0xffffffffu, s, o);

    const float e = 2.0f / (float)(NLEADS - 1);
    float loss = 0.f;
    if (v0) loss += exp2f(e*(s - g0)) * logf(p0);
    if (v1) loss += exp2f(e*(s - g1)) * logf(p1);
    #pragma unroll
    for (int o = 16; o; o >>= 1) loss += __shfl_xor_sync(0xffffffffu, loss, o);
    if (lane == 0) out[b*3 + c] = -loss;
}

// no-ops keep lead_forward_kernel at ncu's relative launch index 3.
__global__ void noop_kernel() {}

extern "C" void kernel_launch(void* const* d_in, const int* in_sizes, int n_in,
                              void* d_out, int out_size)
{
    const float* x   = (const float*)d_in[0];
    const float* w1  = (const float*)d_in[1];
    const float* b1  = (const float*)d_in[2];
    const float* w2  = (const float*)d_in[3];
    const float* b2  = (const float*)d_in[4];
    const float* w3  = (const float*)d_in[5];
    const float* b3  = (const float*)d_in[6];
    const float* w4  = (const float*)d_in[7];
    const float* b4  = (const float*)d_in[8];
    const float* fcw = (const float*)d_in[9];
    const float* fcb = (const float*)d_in[10];
    float* out = (float*)d_out;

    cudaFuncSetAttribute(lead_forward_kernel,
                         cudaFuncAttributeMaxDynamicSharedMemorySize, SMEM_BYTES);

    noop_kernel<<<1, 32>>>();
    noop_kernel<<<1, 32>>>();
    fold_fc_kernel<<<NLEADS, 256>>>(w4, b4, fcw, fcb);   // launch idx 2
    dim3 grid(NB, NLEADS);
    lead_forward_kernel<<<grid, 256, SMEM_BYTES>>>(x, w1, b1, w2, b2, w3, b3,
                                                   w4, b4, fcw, fcb);  // idx 3
    loss_kernel<<<NB, 96>>>(out);
}

// round 15
// speedup vs baseline: 1.3344x; 1.0020x over previous
#include <cuda_runtime.h>
#include <math.h>

#define NLEADS 61
#define NB 128
typedef unsigned long long ull;

__device__ float g_preds[NB * NLEADS * 3];
// folded FC: W_eff[l][3][256] = fcw[l] @ w4[l];  b_eff[l][3] = fcw@b4 + fcb
__device__ float g_weff[NLEADS * 3 * 256];
__device__ float g_beff[NLEADS * 3];

// ---------------- packed fp32x2 ops (Blackwell) ----------------
__device__ __forceinline__ ull ffma2(ull a, ull b, ull c) {
    ull d;
    asm("fma.rn.f32x2 %0, %1, %2, %3;" : "=l"(d) : "l"(a), "l"(b), "l"(c));
    return d;
}
__device__ __forceinline__ ull pk(float lo, float hi) {
    ull r;
    asm("mov.b64 %0, {%1, %2};" : "=l"(r) : "f"(lo), "f"(hi));
    return r;
}
__device__ __forceinline__ float2 upk(ull v) {
    float2 f;
    asm("mov.b64 {%0, %1}, %2;" : "=f"(f.x), "=f"(f.y) : "l"(v));
    return f;
}
__device__ __forceinline__ float hsum(ull v) {
    const float2 f = upk(v);
    return f.x + f.y;
}

// ---- shared memory layout (floats), 13884 fl = 55.5 KB -> 4 CTAs/SM ----
// A1 stored SPLIT: even columns plane E [8][18][34] then odd plane O.
#define OFF_A1E 0        // 4896 fl
#define OFF_A1O 4896     // 4896 fl (A1 region total 9792)
#define OFF_W1D 9792     // 192 fl (dup pairs)
#define OFF_W2D 9984     // 3072 fl (dup pairs)
#define OFF_B1  13056    // 8
#define OFF_B2  13064    // 16
#define OFF_B3  13080    // 32
#define OFF_WEFF 13112   // 772 fl: W_eff (768) + b_eff (3) + pad
#define SMEM_FLOATS 13884
#define SMEM_BYTES (SMEM_FLOATS*4)   // 55536

// aliases inside the A1 region (valid after L2's read-complete sync)
#define OFF_W3  0        // 6144 fl (RAW w3; natural tap pairs)
#define OFF_A2P 6144     // [16][6][20] = 1920 fl (16B aligned)
#define OFF_A3  8064     // 256 fl (16B aligned)
#define OFF_LG  8320     // 4

__global__ void __launch_bounds__(256, 4)
lead_forward_kernel(const float* __restrict__ x,
                    const float* __restrict__ w1g, const float* __restrict__ b1g,
                    const float* __restrict__ w2g, const float* __restrict__ b2g,
                    const float* __restrict__ w3g, const float* __restrict__ b3g,
                    const float* __restrict__ w4g, const float* __restrict__ b4g,
                    const float* __restrict__ fcw, const float* __restrict__ fcb)
{
    extern __shared__ float sm[];
    float*  sA1E = sm + OFF_A1E;
    float*  sA1O = sm + OFF_A1O;
    float*  sA2p = sm + OFF_A2P;
    float*  sA3  = sm + OFF_A3;
    float*  sLg  = sm + OFF_LG;
    float*  sw1d = sm + OFF_W1D;
    float*  sw2d = sm + OFF_W2D;
    float*  sw3  = sm + OFF_W3;
    float*  sb1  = sm + OFF_B1;
    float*  sb2  = sm + OFF_B2;
    float*  sb3  = sm + OFF_B3;
    float*  swef = sm + OFF_WEFF;

    const int tid = threadIdx.x;
    const int b = blockIdx.x;
    const int l = blockIdx.y;
    const float2 z2 = make_float2(0.f, 0.f);
    const float2* x2 = (const float2*)(x + ((size_t)(b*NLEADS + l))*8000);

    // ---- init: zero ONLY the A1 halo (split layout) ----
    // rows 0 and 17 of every plane in BOTH arrays (34 fl = 17 float2 each)
    for (int i = tid; i < 8*2*17; i += 256) {
        const int pl = i / 34, sub = i % 34;
        const int row = (sub >= 17) ? 17 : 0;
        const int c2  = sub % 17;
        ((float2*)(sA1E + pl*612 + row*34))[c2] = z2;
        ((float2*)(sA1O + pl*612 + row*34))[c2] = z2;
    }
    // rows 1..16: E col 0 (orig col 0), E cols 32,33 (orig 64,66),
    //             O cols 32,33 (orig 65,67)
    if (tid < 128) {
        const int pl = tid >> 4, r = (tid & 15) + 1;
        sA1E[pl*612 + r*34] = 0.0f;
        ((float2*)(sA1E + pl*612 + r*34 + 32))[0] = z2;
        ((float2*)(sA1O + pl*612 + r*34 + 32))[0] = z2;
    }
    // ---- stage dup weight pairs + biases ----
    if (tid < 96) {
        const float v = w1g[l*96 + tid];
        ((float2*)sw1d)[tid] = make_float2(v, v);
    }
    #pragma unroll
    for (int k = 0; k < 6; k++) {
        const int i = tid + k*256;     // 1536 = 6*256 exactly, no guard
        const float v = w2g[l*1536 + i];
        ((float2*)sw2d)[i] = make_float2(v, v);
    }
    if (tid < 8)  sb1[tid] = b1g[l*8 + tid];
    if (tid < 16) sb2[tid] = b2g[l*16 + tid];
    if (tid < 32) sb3[tid] = b3g[l*32 + tid];
    __syncthreads();

    // =====================================================================
    // Layer 1 (pooled-row PAIRS): conv (1->8, 3x4, s(1,2), pad (1,1)(2,2))
    // + pool + relu -> pooled (8,16,63) into split A1 (E/O by col parity).
    // =====================================================================
    for (int pair = tid; pair < 8*63; pair += 256) {
        const int pp = pair / 63, pw = pair - pp*63;
        ull P[6][4];
        #pragma unroll
        for (int r = 0; r < 6; r++) {
            const int sr = 4*pp - 1 + r;                 // x row
            const bool rv = (sr >= 0) & (sr < 32);
            const float2* rp = x2 + sr*125 + (2*pw - 1);
            const float2 pA = (rv && pw > 0)  ? rp[0] : z2;
            const float2 pB =  rv             ? rp[1] : z2;
            const float2 pC = (rv && pw < 62) ? rp[2] : z2;
            P[r][0] = pk(pA.x, pB.x);
            P[r][1] = pk(pA.y, pB.y);
            P[r][2] = pk(pB.x, pC.x);
            P[r][3] = pk(pB.y, pC.y);
        }
        // output stored col j = pw+1 -> E plane if j even else O plane
        const int j = pw + 1;
        float* outb = ((j & 1) ? (sA1O + ((j - 1) >> 1)) : (sA1E + (j >> 1)))
                      + (2*pp + 1)*34;
        #pragma unroll
        for (int co = 0; co < 8; co++) {
            const ulonglong2* wq = (const ulonglong2*)(sw1d + co*24);
            ull a0=0ull, a1=0ull, a2=0ull, a3=0ull;
            #pragma unroll
            for (int jj = 0; jj < 6; jj++) {
                const ulonglong2 q = wq[jj];
                {   const int t = 2*jj, kh = t>>2, kw = t&3;
                    a0 = ffma2(P[kh+0][kw], q.x, a0);
                    a1 = ffma2(P[kh+1][kw], q.x, a1);
                    a2 = ffma2(P[kh+2][kw], q.x, a2);
                    a3 = ffma2(P[kh+3][kw], q.x, a3); }
                {   const int t = 2*jj+1, kh = t>>2, kw = t&3;
                    a0 = ffma2(P[kh+0][kw], q.y, a0);
                    a1 = ffma2(P[kh+1][kw], q.y, a1);
                    a2 = ffma2(P[kh+2][kw], q.y, a2);
                    a3 = ffma2(P[kh+3][kw], q.y, a3); }
            }
            const float bias = sb1[co];
            const float2 f0 = upk(a0), f1 = upk(a1), f2 = upk(a2), f3 = upk(a3);
            const float m0 = fmaxf(fmaxf(f0.x, f0.y), fmaxf(f1.x, f1.y)) + bias;
            const float m1 = fmaxf(fmaxf(f2.x, f2.y), fmaxf(f3.x, f3.y)) + bias;
            outb[co*612]      = fmaxf(m0, 0.0f);
            outb[co*612 + 34] = fmaxf(m1, 0.0f);
        }
    }
    __syncthreads();

    // =====================================================================
    // Layer 2 (R8 mapping, SPLIT reads): conv (8->16, 4x3, s(2,2), pad 1)
    // + pool + relu. (8,16,63) -> pooled (16,4,16).
    // =====================================================================
    {
        const int pos = tid & 63;
        const int cg  = tid >> 6;
        const int ph = pos >> 4, pw = pos & 15;
        ull a0[4], a1[4];
        #pragma unroll
        for (int i = 0; i < 4; i++) { a0[i] = 0ull; a1[i] = 0ull; }

        #pragma unroll 1
        for (int ci = 0; ci < 8; ci++) {
            ull P[6][3];
            #pragma unroll
            for (int r = 0; r < 6; r++) {
                const int off = ci*612 + (4*ph + r)*34 + 2*pw;
                const ull pe = *(const ull*)(sA1E + off);      // (X0, X2)
                const ull po = *(const ull*)(sA1O + off);      // (X1, X3)
                const float x4 = sA1E[off + 2];                // X4
                P[r][0] = pe;
                P[r][1] = po;
                P[r][2] = pk(upk(pe).y, x4);                   // (X2, X4)
            }
            #pragma unroll
            for (int i = 0; i < 4; i++) {
                const int co = cg*4 + i;
                const ulonglong2* wq = (const ulonglong2*)(sw2d + (co*8 + ci)*24);
                #pragma unroll
                for (int jj = 0; jj < 6; jj++) {
                    const ulonglong2 q = wq[jj];
                    const int t0 = 2*jj, t1 = 2*jj + 1;
                    a0[i] = ffma2(P[t0/3][t0%3],     q.x, a0[i]);
                    a1[i] = ffma2(P[t0/3 + 2][t0%3], q.x, a1[i]);
                    a0[i] = ffma2(P[t1/3][t1%3],     q.y, a0[i]);
                    a1[i] = ffma2(P[t1/3 + 2][t1%3], q.y, a1[i]);
                }
            }
        }
        __syncthreads();   // ALL A1 reads done -> safe to overwrite region
        #pragma unroll
        for (int i = 0; i < 4; i++) {
            const int co = cg*4 + i;
            const float2 f0 = upk(a0[i]), f1 = upk(a1[i]);
            const float m = fmaxf(fmaxf(f0.x, f0.y), fmaxf(f1.x, f1.y)) + sb2[co];
            sA2p[co*(6*20) + (ph+1)*20 + (pw+1)] = fmaxf(m, 0.0f);
        }
        // zero A2p halo (rows 0,5 and cols 0,17..19 of each [6][20] plane)
        for (int i = tid; i < 16*20; i += 256) {
            const int ci2 = i / 20, c = i % 20;
            sA2p[ci2*120 + 0*20 + c]  = 0.0f;
            sA2p[ci2*120 + 5*20 + c]  = 0.0f;
        }
        for (int i = tid; i < 16*4; i += 256) {
            const int ci2 = i / 4, r = (i & 3) + 1;
            float* row = sA2p + ci2*120 + r*20;
            row[0] = 0.0f; row[17] = 0.0f; row[18] = 0.0f; row[19] = 0.0f;
        }
    }
    // stage RAW w3 into freed A1 head (coalesced float4)
    {
        const float4* w34 = (const float4*)(w3g + (size_t)l*6144);
        #pragma unroll
        for (int k = 0; k < 6; k++) ((float4*)sw3)[tid + k*256] = w34[tid + k*256];
    }
    __syncthreads();

    // =====================================================================
    // Layer 3 (TAP-PAIRED, 128 threads) + W_eff prefetch (other 128 threads).
    // =====================================================================
    if (tid < 128) {
        const int cp  = tid >> 3;
        const int pos = tid & 7;
        const int ph = pos >> 2, pw = pos & 3;
        ull vA0[2], vA1[2], vB0[2], vB1[2];
        #pragma unroll
        for (int c = 0; c < 2; c++) { vA0[c]=vA1[c]=vB0[c]=vB1[c]=0ull; }

        #pragma unroll 1
        for (int ci = 0; ci < 16; ci++) {
            ull p0[4], p1[4], p2[4];
            #pragma unroll
            for (int r = 0; r < 4; r++) {
                const int base = ci*120 + (2*ph + r)*20 + 4*pw;
                const ulonglong2 q = *(const ulonglong2*)(sA2p + base);
                p0[r] = q.x; p1[r] = q.y;
                p2[r] = *(const ull*)(sA2p + base + 4);
            }
            #pragma unroll
            for (int c = 0; c < 2; c++) {
                const int co = cp*2 + c;
                const ulonglong2* wq = (const ulonglong2*)(sw3 + (co*16 + ci)*12);
                const ulonglong2 q0 = wq[0];
                const ulonglong2 q1 = wq[1];
                const ulonglong2 q2 = wq[2];
                vA0[c] = ffma2(p0[0], q0.x, vA0[c]); vA0[c] = ffma2(p1[0], q0.y, vA0[c]);
                vA0[c] = ffma2(p0[1], q1.x, vA0[c]); vA0[c] = ffma2(p1[1], q1.y, vA0[c]);
                vA0[c] = ffma2(p0[2], q2.x, vA0[c]); vA0[c] = ffma2(p1[2], q2.y, vA0[c]);

                vA1[c] = ffma2(p0[1], q0.x, vA1[c]); vA1[c] = ffma2(p1[1], q0.y, vA1[c]);
                vA1[c] = ffma2(p0[2], q1.x, vA1[c]); vA1[c] = ffma2(p1[2], q1.y, vA1[c]);
                vA1[c] = ffma2(p0[3], q2.x, vA1[c]); vA1[c] = ffma2(p1[3], q2.y, vA1[c]);

                vB0[c] = ffma2(p1[0], q0.x, vB0[c]); vB0[c] = ffma2(p2[0], q0.y, vB0[c]);
                vB0[c] = ffma2(p1[1], q1.x, vB0[c]); vB0[c] = ffma2(p2[1], q1.y, vB0[c]);
                vB0[c] = ffma2(p1[2], q2.x, vB0[c]); vB0[c] = ffma2(p2[2], q2.y, vB0[c]);

                vB1[c] = ffma2(p1[1], q0.x, vB1[c]); vB1[c] = ffma2(p2[1], q0.y, vB1[c]);
                vB1[c] = ffma2(p1[2], q1.x, vB1[c]); vB1[c] = ffma2(p2[2], q1.y, vB1[c]);
                vB1[c] = ffma2(p1[3], q2.x, vB1[c]); vB1[c] = ffma2(p2[3], q2.y, vB1[c]);
            }
        }
        #pragma unroll
        for (int c = 0; c < 2; c++) {
            const int co = cp*2 + c;
            const float a0 = hsum(vA0[c]), a1 = hsum(vA1[c]);
            const float b0 = hsum(vB0[c]), b1 = hsum(vB1[c]);
            const float m = fmaxf(fmaxf(a0, b0), fmaxf(a1, b1)) + sb3[co];
            sA3[co*8 + pos] = fmaxf(m, 0.0f);
        }
    } else {
        // idle half-block prefetches this lead's folded FC weights into smem
        const int i = tid - 128;    // 0..127
        const float4* weff4 = (const float4*)(g_weff + (size_t)l*768);
        float4* swef4 = (float4*)swef;
        #pragma unroll
        for (int k = 0; k < 2; k++) {
            const int idx = i + k*128;
            if (idx < 192) swef4[idx] = weff4[idx];
        }
        if (i < 3) swef[768 + i] = g_beff[l*3 + i];
    }
    __syncthreads();

    // =====================================================================
    // Folded L4+FC (smem-hot): logits[c] = W_eff[l][c] . a3 + b_eff[l][c]
    // =====================================================================
    if (tid < 96) {
        const int c = tid >> 5, lane = tid & 31;
        const ulonglong2* wv = (const ulonglong2*)(swef + c*256) + lane*2;
        const ulonglong2* av = (const ulonglong2*)sA3 + lane*2;
        const ulonglong2 w0 = wv[0], w1 = wv[1];
        const ulonglong2 v0 = av[0], v1 = av[1];
        ull acc = ffma2(w0.x, v0.x, 0ull);
        acc = ffma2(w0.y, v0.y, acc);
        acc = ffma2(w1.x, v1.x, acc);
        acc = ffma2(w1.y, v1.y, acc);
        float s = hsum(acc);
        #pragma unroll
        for (int o = 16; o; o >>= 1) s += __shfl_xor_sync(0xffffffffu, s, o);
        if (lane == 0) sLg[c] = s + swef[768 + c];
    }
    __syncthreads();

    // ---- softmax, one thread ----
    if (tid == 0) {
        const float m = fmaxf(sLg[0], fmaxf(sLg[1], sLg[2]));
        const float e0 = expf(sLg[0]-m), e1 = expf(sLg[1]-m), e2 = expf(sLg[2]-m);
        const float inv = 1.0f / (e0 + e1 + e2);
        float* outp = g_preds + ((size_t)(b*NLEADS + l))*3;
        outp[0] = e0*inv; outp[1] = e1*inv; outp[2] = e2*inv;
    }
}

// =====================================================================
// Fold kernel: per lead l, W_eff[c][k] = sum_co fcw[c,co]*w4[co,k];
// b_eff[c] = sum_co fcw[c,co]*b4[co] + fcb[c].  Grid 61 x 256 threads.
// =====================================================================
__global__ void fold_fc_kernel(const float* __restrict__ w4g,
                               const float* __restrict__ b4g,
                               const float* __restrict__ fcw,
                               const float* __restrict__ fcb)
{
    __shared__ float sfc[192];
    const int l = blockIdx.x;
    const int tid = threadIdx.x;
    if (tid < 192) sfc[tid] = fcw[l*192 + tid];
    __syncthreads();

    const float* w4l = w4g + (size_t)l*64*256;
    float acc0 = 0.f, acc1 = 0.f, acc2 = 0.f;
    #pragma unroll 4
    for (int co = 0; co < 64; co++) {
        const float v = w4l[co*256 + tid];   // coalesced across tid
        acc0 += sfc[co]       * v;
        acc1 += sfc[64 + co]  * v;
        acc2 += sfc[128 + co] * v;
    }
    g_weff[((size_t)l*3 + 0)*256 + tid] = acc0;
    g_weff[((size_t)l*3 + 1)*256 + tid] = acc1;
    g_weff[((size_t)l*3 + 2)*256 + tid] = acc2;

    if (tid < 3) {
        float a = fcb[l*3 + tid];
        for (int co = 0; co < 64; co++) a += sfc[tid*64 + co] * b4g[l*64 + co];
        g_beff[l*3 + tid] = a;
    }
}

// =====================================================================
// Fusion loss in log2 space. One block per batch, one warp per class.
// =====================================================================
__global__ void loss_kernel(float* __restrict__ out)
{
    const int b = blockIdx.x;
    const int c = threadIdx.x >> 5;
    const int lane = threadIdx.x & 31;
    const float* p = g_preds + (size_t)b*NLEADS*3 + c;

    const int l0 = lane, l1 = lane + 32;
    const bool v0 = l0 < NLEADS, v1 = l1 < NLEADS;
    float p0 = 1.f, p1 = 1.f, g0 = 0.f, g1 = 0.f, s = 0.f;
    if (v0) { p0 = p[l0*3]; g0 = log2f(1.0f - p0); s += g0; }
    if (v1) { p1 = p[l1*3]; g1 = log2f(1.0f - p1); s += g1; }
    #pragma unroll
    for (int o = 16; o; o >>= 1) s += __shfl_xor_sync(0xffffffffu, s, o);

    const float e = 2.0f / (float)(NLEADS - 1);
    float loss = 0.f;
    if (v0) loss += exp2f(e*(s - g0)) * logf(p0);
    if (v1) loss += exp2f(e*(s - g1)) * logf(p1);
    #pragma unroll
    for (int o = 16; o; o >>= 1) loss += __shfl_xor_sync(0xffffffffu, loss, o);
    if (lane == 0) out[b*3 + c] = -loss;
}

extern "C" void kernel_launch(void* const* d_in, const int* in_sizes, int n_in,
                              void* d_out, int out_size)
{
    const float* x   = (const float*)d_in[0];
    const float* w1  = (const float*)d_in[1];
    const float* b1  = (const float*)d_in[2];
    const float* w2  = (const float*)d_in[3];
    const float* b2  = (const float*)d_in[4];
    const float* w3  = (const float*)d_in[5];
    const float* b3  = (const float*)d_in[6];
    const float* w4  = (const float*)d_in[7];
    const float* b4  = (const float*)d_in[8];
    const float* fcw = (const float*)d_in[9];
    const float* fcb = (const float*)d_in[10];
    float* out = (float*)d_out;

    cudaFuncSetAttribute(lead_forward_kernel,
                         cudaFuncAttributeMaxDynamicSharedMemorySize, SMEM_BYTES);

    fold_fc_kernel<<<NLEADS, 256>>>(w4, b4, fcw, fcb);
    dim3 grid(NB, NLEADS);
    lead_forward_kernel<<<grid, 256, SMEM_BYTES>>>(x, w1, b1, w2, b2, w3, b3,
                                                   w4, b4, fcw, fcb);
    loss_kernel<<<NB, 96>>>(out);
}

// round 16
// speedup vs baseline: 1.3485x; 1.0106x over previous
#include <cuda_runtime.h>
#include <math.h>

#define NLEADS 61
#define NB 128
typedef unsigned long long ull;

__device__ float g_preds[NB * NLEADS * 3];
// folded FC: W_eff[l][3][256] = fcw[l] @ w4[l];  b_eff[l][3] = fcw@b4 + fcb
__device__ float g_weff[NLEADS * 3 * 256];
__device__ float g_beff[NLEADS * 3];

// ---------------- packed fp32x2 ops (Blackwell) ----------------
__device__ __forceinline__ ull ffma2(ull a, ull b, ull c) {
    ull d;
    asm("fma.rn.f32x2 %0, %1, %2, %3;" : "=l"(d) : "l"(a), "l"(b), "l"(c));
    return d;
}
__device__ __forceinline__ ull pk(float lo, float hi) {
    ull r;
    asm("mov.b64 %0, {%1, %2};" : "=l"(r) : "f"(lo), "f"(hi));
    return r;
}
__device__ __forceinline__ float2 upk(ull v) {
    float2 f;
    asm("mov.b64 {%0, %1}, %2;" : "=f"(f.x), "=f"(f.y) : "l"(v));
    return f;
}
__device__ __forceinline__ float hsum(ull v) {
    const float2 f = upk(v);
    return f.x + f.y;
}

// ---- shared memory layout (floats), 13884 fl = 55.5 KB -> 4 CTAs/SM ----
// A1 stored SPLIT: even columns plane E [8][18][34] then odd plane O.
#define OFF_A1E 0        // 4896 fl
#define OFF_A1O 4896     // 4896 fl (A1 region total 9792)
#define OFF_W1D 9792     // 192 fl (dup pairs)
#define OFF_W2D 9984     // 3072 fl (dup pairs)
#define OFF_B1  13056    // 8
#define OFF_B2  13064    // 16
#define OFF_B3  13080    // 32
#define OFF_WEFF 13112   // 772 fl: W_eff (768) + b_eff (3) + pad
#define SMEM_FLOATS 13884
#define SMEM_BYTES (SMEM_FLOATS*4)   // 55536

// aliases inside the A1 region (valid after L2's read-complete sync)
#define OFF_W3  0        // 6144 fl (RAW w3; natural tap pairs)
#define OFF_A2P 6144     // [16][6][20] = 1920 fl (16B aligned)
#define OFF_A3  8064     // 256 fl (16B aligned)
#define OFF_LG  8320     // 4

__global__ void __launch_bounds__(256, 4)
lead_forward_kernel(const float* __restrict__ x,
                    const float* __restrict__ w1g, const float* __restrict__ b1g,
                    const float* __restrict__ w2g, const float* __restrict__ b2g,
                    const float* __restrict__ w3g, const float* __restrict__ b3g,
                    const float* __restrict__ w4g, const float* __restrict__ b4g,
                    const float* __restrict__ fcw, const float* __restrict__ fcb)
{
    extern __shared__ float sm[];
    float*  sA1E = sm + OFF_A1E;
    float*  sA1O = sm + OFF_A1O;
    float*  sA2p = sm + OFF_A2P;
    float*  sA3  = sm + OFF_A3;
    float*  sLg  = sm + OFF_LG;
    float*  sw1d = sm + OFF_W1D;
    float*  sw2d = sm + OFF_W2D;
    float*  sw3  = sm + OFF_W3;
    float*  sb1  = sm + OFF_B1;
    float*  sb2  = sm + OFF_B2;
    float*  sb3  = sm + OFF_B3;
    float*  swef = sm + OFF_WEFF;

    const int tid = threadIdx.x;
    const int b = blockIdx.x;
    const int l = blockIdx.y;
    const float2 z2 = make_float2(0.f, 0.f);
    const float2* x2 = (const float2*)(x + ((size_t)(b*NLEADS + l))*8000);

    // ---- init: zero ONLY the A1 halo (split layout) ----
    for (int i = tid; i < 8*2*17; i += 256) {
        const int pl = i / 34, sub = i % 34;
        const int row = (sub >= 17) ? 17 : 0;
        const int c2  = sub % 17;
        ((float2*)(sA1E + pl*612 + row*34))[c2] = z2;
        ((float2*)(sA1O + pl*612 + row*34))[c2] = z2;
    }
    if (tid < 128) {
        const int pl = tid >> 4, r = (tid & 15) + 1;
        sA1E[pl*612 + r*34] = 0.0f;
        ((float2*)(sA1E + pl*612 + r*34 + 32))[0] = z2;
        ((float2*)(sA1O + pl*612 + r*34 + 32))[0] = z2;
    }
    // ---- stage dup weight pairs + biases ----
    if (tid < 96) {
        const float v = w1g[l*96 + tid];
        ((float2*)sw1d)[tid] = make_float2(v, v);
    }
    #pragma unroll
    for (int k = 0; k < 6; k++) {
        const int i = tid + k*256;     // 1536 = 6*256 exactly, no guard
        const float v = w2g[l*1536 + i];
        ((float2*)sw2d)[i] = make_float2(v, v);
    }
    if (tid < 8)  sb1[tid] = b1g[l*8 + tid];
    if (tid < 16) sb2[tid] = b2g[l*16 + tid];
    if (tid < 32) sb3[tid] = b3g[l*32 + tid];
    __syncthreads();

    // =====================================================================
    // Layer 1 (pooled-row PAIRS): conv (1->8, 3x4, s(1,2), pad (1,1)(2,2))
    // + pool + relu -> pooled (8,16,63) into split A1 (E/O by col parity).
    // =====================================================================
    for (int pair = tid; pair < 8*63; pair += 256) {
        const int pp = pair / 63, pw = pair - pp*63;
        ull P[6][4];
        #pragma unroll
        for (int r = 0; r < 6; r++) {
            const int sr = 4*pp - 1 + r;                 // x row
            const bool rv = (sr >= 0) & (sr < 32);
            const float2* rp = x2 + sr*125 + (2*pw - 1);
            const float2 pA = (rv && pw > 0)  ? rp[0] : z2;
            const float2 pB =  rv             ? rp[1] : z2;
            const float2 pC = (rv && pw < 62) ? rp[2] : z2;
            P[r][0] = pk(pA.x, pB.x);
            P[r][1] = pk(pA.y, pB.y);
            P[r][2] = pk(pB.x, pC.x);
            P[r][3] = pk(pB.y, pC.y);
        }
        // output stored col j = pw+1 -> E plane if j even else O plane
        const int j = pw + 1;
        float* outb = ((j & 1) ? (sA1O + ((j - 1) >> 1)) : (sA1E + (j >> 1)))
                      + (2*pp + 1)*34;
        #pragma unroll
        for (int co = 0; co < 8; co++) {
            const ulonglong2* wq = (const ulonglong2*)(sw1d + co*24);
            ull a0=0ull, a1=0ull, a2=0ull, a3=0ull;
            #pragma unroll
            for (int jj = 0; jj < 6; jj++) {
                const ulonglong2 q = wq[jj];
                {   const int t = 2*jj, kh = t>>2, kw = t&3;
                    a0 = ffma2(P[kh+0][kw], q.x, a0);
                    a1 = ffma2(P[kh+1][kw], q.x, a1);
                    a2 = ffma2(P[kh+2][kw], q.x, a2);
                    a3 = ffma2(P[kh+3][kw], q.x, a3); }
                {   const int t = 2*jj+1, kh = t>>2, kw = t&3;
                    a0 = ffma2(P[kh+0][kw], q.y, a0);
                    a1 = ffma2(P[kh+1][kw], q.y, a1);
                    a2 = ffma2(P[kh+2][kw], q.y, a2);
                    a3 = ffma2(P[kh+3][kw], q.y, a3); }
            }
            const float bias = sb1[co];
            const float2 f0 = upk(a0), f1 = upk(a1), f2 = upk(a2), f3 = upk(a3);
            const float m0 = fmaxf(fmaxf(f0.x, f0.y), fmaxf(f1.x, f1.y)) + bias;
            const float m1 = fmaxf(fmaxf(f2.x, f2.y), fmaxf(f3.x, f3.y)) + bias;
            outb[co*612]      = fmaxf(m0, 0.0f);
            outb[co*612 + 34] = fmaxf(m1, 0.0f);
        }
    }
    __syncthreads();

    // =====================================================================
    // Layer 2 (R8 mapping, SPLIT reads): conv (8->16, 4x3, s(2,2), pad 1)
    // + pool + relu. (8,16,63) -> pooled (16,4,16).
    // =====================================================================
    {
        const int pos = tid & 63;
        const int cg  = tid >> 6;
        const int ph = pos >> 4, pw = pos & 15;
        ull a0[4], a1[4];
        #pragma unroll
        for (int i = 0; i < 4; i++) { a0[i] = 0ull; a1[i] = 0ull; }

        #pragma unroll 1
        for (int ci = 0; ci < 8; ci++) {
            ull P[6][3];
            #pragma unroll
            for (int r = 0; r < 6; r++) {
                const int off = ci*612 + (4*ph + r)*34 + 2*pw;
                const ull pe = *(const ull*)(sA1E + off);      // (X0, X2)
                const ull po = *(const ull*)(sA1O + off);      // (X1, X3)
                const float x4 = sA1E[off + 2];                // X4
                P[r][0] = pe;
                P[r][1] = po;
                P[r][2] = pk(upk(pe).y, x4);                   // (X2, X4)
            }
            #pragma unroll
            for (int i = 0; i < 4; i++) {
                const int co = cg*4 + i;
                const ulonglong2* wq = (const ulonglong2*)(sw2d + (co*8 + ci)*24);
                #pragma unroll
                for (int jj = 0; jj < 6; jj++) {
                    const ulonglong2 q = wq[jj];
                    const int t0 = 2*jj, t1 = 2*jj + 1;
                    a0[i] = ffma2(P[t0/3][t0%3],     q.x, a0[i]);
                    a1[i] = ffma2(P[t0/3 + 2][t0%3], q.x, a1[i]);
                    a0[i] = ffma2(P[t1/3][t1%3],     q.y, a0[i]);
                    a1[i] = ffma2(P[t1/3 + 2][t1%3], q.y, a1[i]);
                }
            }
        }
        __syncthreads();   // ALL A1 reads done -> safe to overwrite region
        #pragma unroll
        for (int i = 0; i < 4; i++) {
            const int co = cg*4 + i;
            const float2 f0 = upk(a0[i]), f1 = upk(a1[i]);
            const float m = fmaxf(fmaxf(f0.x, f0.y), fmaxf(f1.x, f1.y)) + sb2[co];
            sA2p[co*(6*20) + (ph+1)*20 + (pw+1)] = fmaxf(m, 0.0f);
        }
        // zero A2p halo (rows 0,5 and cols 0,17..19 of each [6][20] plane)
        for (int i = tid; i < 16*20; i += 256) {
            const int ci2 = i / 20, c = i % 20;
            sA2p[ci2*120 + 0*20 + c]  = 0.0f;
            sA2p[ci2*120 + 5*20 + c]  = 0.0f;
        }
        for (int i = tid; i < 16*4; i += 256) {
            const int ci2 = i / 4, r = (i & 3) + 1;
            float* row = sA2p + ci2*120 + r*20;
            row[0] = 0.0f; row[17] = 0.0f; row[18] = 0.0f; row[19] = 0.0f;
        }
    }
    // stage RAW w3 into freed A1 head (coalesced float4)
    {
        const float4* w34 = (const float4*)(w3g + (size_t)l*6144);
        #pragma unroll
        for (int k = 0; k < 6; k++) ((float4*)sw3)[tid + k*256] = w34[tid + k*256];
    }
    __syncthreads();

    // =====================================================================
    // Layer 3 (TAP-PAIRED, 128 threads) + W_eff prefetch (other 128 threads).
    // =====================================================================
    if (tid < 128) {
        const int cp  = tid >> 3;
        const int pos = tid & 7;
        const int ph = pos >> 2, pw = pos & 3;
        ull vA0[2], vA1[2], vB0[2], vB1[2];
        #pragma unroll
        for (int c = 0; c < 2; c++) { vA0[c]=vA1[c]=vB0[c]=vB1[c]=0ull; }

        #pragma unroll 1
        for (int ci = 0; ci < 16; ci++) {
            ull p0[4], p1[4], p2[4];
            #pragma unroll
            for (int r = 0; r < 4; r++) {
                const int base = ci*120 + (2*ph + r)*20 + 4*pw;
                const ulonglong2 q = *(const ulonglong2*)(sA2p + base);
                p0[r] = q.x; p1[r] = q.y;
                p2[r] = *(const ull*)(sA2p + base + 4);
            }
            #pragma unroll
            for (int c = 0; c < 2; c++) {
                const int co = cp*2 + c;
                const ulonglong2* wq = (const ulonglong2*)(sw3 + (co*16 + ci)*12);
                const ulonglong2 q0 = wq[0];
                const ulonglong2 q1 = wq[1];
                const ulonglong2 q2 = wq[2];
                vA0[c] = ffma2(p0[0], q0.x, vA0[c]); vA0[c] = ffma2(p1[0], q0.y, vA0[c]);
                vA0[c] = ffma2(p0[1], q1.x, vA0[c]); vA0[c] = ffma2(p1[1], q1.y, vA0[c]);
                vA0[c] = ffma2(p0[2], q2.x, vA0[c]); vA0[c] = ffma2(p1[2], q2.y, vA0[c]);

                vA1[c] = ffma2(p0[1], q0.x, vA1[c]); vA1[c] = ffma2(p1[1], q0.y, vA1[c]);
                vA1[c] = ffma2(p0[2], q1.x, vA1[c]); vA1[c] = ffma2(p1[2], q1.y, vA1[c]);
                vA1[c] = ffma2(p0[3], q2.x, vA1[c]); vA1[c] = ffma2(p1[3], q2.y, vA1[c]);

                vB0[c] = ffma2(p1[0], q0.x, vB0[c]); vB0[c] = ffma2(p2[0], q0.y, vB0[c]);
                vB0[c] = ffma2(p1[1], q1.x, vB0[c]); vB0[c] = ffma2(p2[1], q1.y, vB0[c]);
                vB0[c] = ffma2(p1[2], q2.x, vB0[c]); vB0[c] = ffma2(p2[2], q2.y, vB0[c]);

                vB1[c] = ffma2(p1[1], q0.x, vB1[c]); vB1[c] = ffma2(p2[1], q0.y, vB1[c]);
                vB1[c] = ffma2(p1[2], q1.x, vB1[c]); vB1[c] = ffma2(p2[2], q1.y, vB1[c]);
                vB1[c] = ffma2(p1[3], q2.x, vB1[c]); vB1[c] = ffma2(p2[3], q2.y, vB1[c]);
            }
        }
        #pragma unroll
        for (int c = 0; c < 2; c++) {
            const int co = cp*2 + c;
            const float a0 = hsum(vA0[c]), a1 = hsum(vA1[c]);
            const float b0 = hsum(vB0[c]), b1 = hsum(vB1[c]);
            const float m = fmaxf(fmaxf(a0, b0), fmaxf(a1, b1)) + sb3[co];
            sA3[co*8 + pos] = fmaxf(m, 0.0f);
        }
    } else {
        // idle half-block prefetches this lead's folded FC weights into smem
        const int i = tid - 128;    // 0..127
        const float4* weff4 = (const float4*)(g_weff + (size_t)l*768);
        float4* swef4 = (float4*)swef;
        #pragma unroll
        for (int k = 0; k < 2; k++) {
            const int idx = i + k*128;
            if (idx < 192) swef4[idx] = weff4[idx];
        }
        if (i < 3) swef[768 + i] = g_beff[l*3 + i];
    }
    __syncthreads();

    // =====================================================================
    // Folded L4+FC (smem-hot): logits[c] = W_eff[l][c] . a3 + b_eff[l][c]
    // =====================================================================
    if (tid < 96) {
        const int c = tid >> 5, lane = tid & 31;
        const ulonglong2* wv = (const ulonglong2*)(swef + c*256) + lane*2;
        const ulonglong2* av = (const ulonglong2*)sA3 + lane*2;
        const ulonglong2 w0 = wv[0], w1 = wv[1];
        const ulonglong2 v0 = av[0], v1 = av[1];
        ull acc = ffma2(w0.x, v0.x, 0ull);
        acc = ffma2(w0.y, v0.y, acc);
        acc = ffma2(w1.x, v1.x, acc);
        acc = ffma2(w1.y, v1.y, acc);
        float s = hsum(acc);
        #pragma unroll
        for (int o = 16; o; o >>= 1) s += __shfl_xor_sync(0xffffffffu, s, o);
        if (lane == 0) sLg[c] = s + swef[768 + c];
    }
    __syncthreads();

    // ---- softmax, one thread ----
    if (tid == 0) {
        const float m = fmaxf(sLg[0], fmaxf(sLg[1], sLg[2]));
        const float e0 = expf(sLg[0]-m), e1 = expf(sLg[1]-m), e2 = expf(sLg[2]-m);
        const float inv = 1.0f / (e0 + e1 + e2);
        float* outp = g_preds + ((size_t)(b*NLEADS + l))*3;
        outp[0] = e0*inv; outp[1] = e1*inv; outp[2] = e2*inv;
    }
}

// =====================================================================
// Fold kernel v2: grid (61, 3) — one block per (lead, class).
// W_eff[l][c][k] = sum_co fcw[l,c,co] * w4[l,co,k]   (k = tid, coalesced)
// Deep unroll (16) -> 16 independent loads in flight, latency/16 waves.
// =====================================================================
__global__ void fold_fc_kernel(const float* __restrict__ w4g,
                               const float* __restrict__ b4g,
                               const float* __restrict__ fcw,
                               const float* __restrict__ fcb)
{
    __shared__ float sfc[64];
    const int l = blockIdx.x;
    const int c = blockIdx.y;
    const int tid = threadIdx.x;
    if (tid < 64) sfc[tid] = fcw[l*192 + c*64 + tid];
    __syncthreads();

    const float* w4l = w4g + (size_t)l*64*256;
    float acc = 0.f;
    #pragma unroll 16
    for (int co = 0; co < 64; co++)
        acc += sfc[co] * w4l[co*256 + tid];    // coalesced across tid
    g_weff[((size_t)l*3 + c)*256 + tid] = acc;

    if (tid == 0) {
        float a = fcb[l*3 + c];
        for (int co = 0; co < 64; co++) a += sfc[co] * b4g[l*64 + co];
        g_beff[l*3 + c] = a;
    }
}

// =====================================================================
// Fusion loss in log2 space. One block per batch, one warp per class.
// =====================================================================
__global__ void loss_kernel(float* __restrict__ out)
{
    const int b = blockIdx.x;
    const int c = threadIdx.x >> 5;
    const int lane = threadIdx.x & 31;
    const float* p = g_preds + (size_t)b*NLEADS*3 + c;

    const int l0 = lane, l1 = lane + 32;
    const bool v0 = l0 < NLEADS, v1 = l1 < NLEADS;
    float p0 = 1.f, p1 = 1.f, g0 = 0.f, g1 = 0.f, s = 0.f;
    if (v0) { p0 = p[l0*3]; g0 = log2f(1.0f - p0); s += g0; }
    if (v1) { p1 = p[l1*3]; g1 = log2f(1.0f - p1); s += g1; }
    #pragma unroll
    for (int o = 16; o; o >>= 1) s += __shfl_xor_sync(0xffffffffu, s, o);

    const float e = 2.0f / (float)(NLEADS - 1);
    float loss = 0.f;
    if (v0) loss += exp2f(e*(s - g0)) * logf(p0);
    if (v1) loss += exp2f(e*(s - g1)) * logf(p1);
    #pragma unroll
    for (int o = 16; o; o >>= 1) loss += __shfl_xor_sync(0xffffffffu, loss, o);
    if (lane == 0) out[b*3 + c] = -loss;
}

extern "C" void kernel_launch(void* const* d_in, const int* in_sizes, int n_in,
                              void* d_out, int out_size)
{
    const float* x   = (const float*)d_in[0];
    const float* w1  = (const float*)d_in[1];
    const float* b1  = (const float*)d_in[2];
    const float* w2  = (const float*)d_in[3];
    const float* b2  = (const float*)d_in[4];
    const float* w3  = (const float*)d_in[5];
    const float* b3  = (const float*)d_in[6];
    const float* w4  = (const float*)d_in[7];
    const float* b4  = (const float*)d_in[8];
    const float* fcw = (const float*)d_in[9];
    const float* fcb = (const float*)d_in[10];
    float* out = (float*)d_out;

    cudaFuncSetAttribute(lead_forward_kernel,
                         cudaFuncAttributeMaxDynamicSharedMemorySize, SMEM_BYTES);

    dim3 fgrid(NLEADS, 3);
    fold_fc_kernel<<<fgrid, 256>>>(w4, b4, fcw, fcb);
    dim3 grid(NB, NLEADS);
    lead_forward_kernel<<<grid, 256, SMEM_BYTES>>>(x, w1, b1, w2, b2, w3, b3,
                                                   w4, b4, fcw, fcb);
    loss_kernel<<<NB, 96>>>(out);
}